// round 1
// baseline (speedup 1.0000x reference)
#include <cuda_runtime.h>
#include <cstddef>

// Problem constants
constexpr int B   = 2;
constexpr int T   = 2048;
constexpr int DIM = 1024;
constexpr int H   = 16;
constexpr int HD  = 64;           // DIM / H
constexpr int BT  = B * T;        // 4096
constexpr float SCALE = 0.03125f; // 1/sqrt(1024)

constexpr size_t Y_SIZE   = (size_t)BT * DIM;              // 4,194,304
constexpr size_t ATT_SIZE = (size_t)B * H * T * T;         // 134,217,728

// Scratch (allocation-free rule: __device__ globals)
__device__ float g_q[BT * DIM];
__device__ float g_k[BT * DIM];
__device__ float g_v[BT * DIM];
__device__ float g_y[BT * DIM];
__device__ float g_raw[ATT_SIZE];   // raw (scaled) attention scores
__device__ float g_att_fb[1];       // placeholder (att goes to d_out normally)

// ---------------------------------------------------------------------------
// 64x64x16 micro tile: c[4][4] += As[k][ty*4..] * Bs[k][tx*4..]
// ---------------------------------------------------------------------------
__device__ __forceinline__ void mm_tile16(const float (*As)[64], const float (*Bs)[64],
                                          int tx, int ty, float c[4][4]) {
#pragma unroll
    for (int k = 0; k < 16; ++k) {
        float4 a4 = *(const float4*)&As[k][ty * 4];
        float4 b4 = *(const float4*)&Bs[k][tx * 4];
        float av[4] = {a4.x, a4.y, a4.z, a4.w};
        float bv[4] = {b4.x, b4.y, b4.z, b4.w};
#pragma unroll
        for (int i = 0; i < 4; ++i)
#pragma unroll
            for (int j = 0; j < 4; ++j)
                c[i][j] = fmaf(av[i], bv[j], c[i][j]);
    }
}

// ---------------------------------------------------------------------------
// C[M,N] = A[M,K] @ W[N,K]^T   (torch Linear: y = x @ W.T)
// BM=BN=64, BK=16, 256 threads, 4x4 per thread. M,N,K multiples of 64/16.
// ---------------------------------------------------------------------------
__global__ void sgemm_xwT(const float* __restrict__ A, const float* __restrict__ W,
                          float* __restrict__ C, int M, int N, int K) {
    __shared__ float As[16][64];
    __shared__ float Bs[16][64];
    const int tid  = threadIdx.x;
    const int m0   = blockIdx.y * 64;
    const int n0   = blockIdx.x * 64;
    const int lrow = tid >> 2;         // 0..63
    const int lc4  = (tid & 3) * 4;    // 0,4,8,12
    const int tx   = tid & 15;
    const int ty   = tid >> 4;
    float c[4][4] = {};

    for (int k0 = 0; k0 < K; k0 += 16) {
        float4 a = *(const float4*)(A + (size_t)(m0 + lrow) * K + k0 + lc4);
        float4 w = *(const float4*)(W + (size_t)(n0 + lrow) * K + k0 + lc4);
        As[lc4 + 0][lrow] = a.x; As[lc4 + 1][lrow] = a.y;
        As[lc4 + 2][lrow] = a.z; As[lc4 + 3][lrow] = a.w;
        Bs[lc4 + 0][lrow] = w.x; Bs[lc4 + 1][lrow] = w.y;
        Bs[lc4 + 2][lrow] = w.z; Bs[lc4 + 3][lrow] = w.w;
        __syncthreads();
        mm_tile16(As, Bs, tx, ty, c);
        __syncthreads();
    }
#pragma unroll
    for (int i = 0; i < 4; ++i) {
        float* crow = C + (size_t)(m0 + ty * 4 + i) * N + n0 + tx * 4;
        *(float4*)crow = make_float4(c[i][0], c[i][1], c[i][2], c[i][3]);
    }
}

// ---------------------------------------------------------------------------
// Raw scores: raw[bh, i, j] = SCALE * dot(q[b,h,i,:], k[b,h,j,:])
// Skips tiles entirely above the diagonal. HD=64 -> 4 k-steps of 16.
// ---------------------------------------------------------------------------
__global__ void scores_kernel(float* __restrict__ raw) {
    const int bh = blockIdx.z;
    const int b  = bh >> 4;     // /H
    const int h  = bh & 15;     // %H
    const int i0 = blockIdx.y * 64;
    const int j0 = blockIdx.x * 64;
    if (j0 > i0 + 63) return;   // fully masked tile: never read downstream

    const float* qb = g_q + (size_t)b * T * DIM + h * HD;
    const float* kb = g_k + (size_t)b * T * DIM + h * HD;

    __shared__ float As[16][64];
    __shared__ float Bs[16][64];
    const int tid  = threadIdx.x;
    const int lrow = tid >> 2;
    const int lc4  = (tid & 3) * 4;
    const int tx   = tid & 15;
    const int ty   = tid >> 4;
    float c[4][4] = {};

    for (int k0 = 0; k0 < HD; k0 += 16) {
        float4 a = *(const float4*)(qb + (size_t)(i0 + lrow) * DIM + k0 + lc4);
        float4 w = *(const float4*)(kb + (size_t)(j0 + lrow) * DIM + k0 + lc4);
        As[lc4 + 0][lrow] = a.x; As[lc4 + 1][lrow] = a.y;
        As[lc4 + 2][lrow] = a.z; As[lc4 + 3][lrow] = a.w;
        Bs[lc4 + 0][lrow] = w.x; Bs[lc4 + 1][lrow] = w.y;
        Bs[lc4 + 2][lrow] = w.z; Bs[lc4 + 3][lrow] = w.w;
        __syncthreads();
        mm_tile16(As, Bs, tx, ty, c);
        __syncthreads();
    }
    float* out = raw + (size_t)bh * T * T;
#pragma unroll
    for (int i = 0; i < 4; ++i) {
        float* crow = out + (size_t)(i0 + ty * 4 + i) * T + j0 + tx * 4;
        *(float4*)crow = make_float4(c[i][0] * SCALE, c[i][1] * SCALE,
                                     c[i][2] * SCALE, c[i][3] * SCALE);
    }
}

// ---------------------------------------------------------------------------
// Row softmax with causal masking. One block per (bh, i) row.
// Reads raw[j] for j<=i; writes att[j] for ALL j (zeros beyond the diagonal).
// Safe when raw == att (element-wise read-before-write per thread).
// ---------------------------------------------------------------------------
__global__ void softmax_kernel(const float* __restrict__ raw, float* __restrict__ att) {
    const size_t row = blockIdx.x;          // 0 .. B*H*T-1
    const int i = (int)(row & (T - 1));     // row % T
    const float* r = raw + row * (size_t)T;
    float*       o = att + row * (size_t)T;
    const int n = i + 1;
    const int tid = threadIdx.x;

    __shared__ float red[256];

    float mx = -1e30f;
    for (int j = tid; j < n; j += 256) mx = fmaxf(mx, r[j]);
    red[tid] = mx; __syncthreads();
    for (int s = 128; s > 0; s >>= 1) {
        if (tid < s) red[tid] = fmaxf(red[tid], red[tid + s]);
        __syncthreads();
    }
    mx = red[0]; __syncthreads();

    float sum = 0.f;
    for (int j = tid; j < n; j += 256) sum += __expf(r[j] - mx);
    red[tid] = sum; __syncthreads();
    for (int s = 128; s > 0; s >>= 1) {
        if (tid < s) red[tid] += red[tid + s];
        __syncthreads();
    }
    const float inv = 1.f / red[0];

    for (int j = tid; j < T; j += 256)
        o[j] = (j < n) ? __expf(r[j] - mx) * inv : 0.f;
}

// ---------------------------------------------------------------------------
// y[b,h,i,d] = sum_j att[bh,i,j] * v[b,h,j,d].  N=HD=64 full tile.
// Skips j-tiles beyond the causal boundary (att there is exactly 0).
// ---------------------------------------------------------------------------
__global__ void av_kernel(const float* __restrict__ att) {
    const int bh = blockIdx.z;
    const int b  = bh >> 4;
    const int h  = bh & 15;
    const int i0 = blockIdx.y * 64;

    const float* arow = att + (size_t)bh * T * T;
    const float* vb   = g_v + (size_t)b * T * DIM + h * HD;
    float*       yb   = g_y + (size_t)b * T * DIM + h * HD;

    __shared__ float As[16][64];   // As[k][i]  (att tile, transposed)
    __shared__ float Bs[16][64];   // Bs[k][d]  (v tile, natural)
    const int tid  = threadIdx.x;
    const int lrow = tid >> 2;        // att load: row within i-tile
    const int lc4  = (tid & 3) * 4;   // att load: col4 within k-tile
    const int jr   = tid >> 4;        // v load: row within k-tile (0..15)
    const int dc4  = (tid & 15) * 4;  // v load: col within HD
    const int tx   = tid & 15;
    const int ty   = tid >> 4;
    float c[4][4] = {};

    const int kmax = i0 + 64;   // j <= i <= i0+63
    for (int k0 = 0; k0 < kmax; k0 += 16) {
        float4 a = *(const float4*)(arow + (size_t)(i0 + lrow) * T + k0 + lc4);
        As[lc4 + 0][lrow] = a.x; As[lc4 + 1][lrow] = a.y;
        As[lc4 + 2][lrow] = a.z; As[lc4 + 3][lrow] = a.w;
        float4 v = *(const float4*)(vb + (size_t)(k0 + jr) * DIM + dc4);
        *(float4*)&Bs[jr][dc4] = v;
        __syncthreads();
        mm_tile16(As, Bs, tx, ty, c);
        __syncthreads();
    }
#pragma unroll
    for (int i = 0; i < 4; ++i) {
        float* crow = yb + (size_t)(i0 + ty * 4 + i) * DIM + tx * 4;
        *(float4*)crow = make_float4(c[i][0], c[i][1], c[i][2], c[i][3]);
    }
}

// ---------------------------------------------------------------------------
extern "C" void kernel_launch(void* const* d_in, const int* in_sizes, int n_in,
                              void* d_out, int out_size) {
    const float* Q  = (const float*)d_in[0];
    const float* K  = (const float*)d_in[1];
    const float* V  = (const float*)d_in[2];
    const float* Wq = (const float*)d_in[3];
    const float* Wk = (const float*)d_in[4];
    const float* Wv = (const float*)d_in[5];
    const float* Wo = (const float*)d_in[6];
    float* out = (float*)d_out;

    float *gq, *gk, *gv, *gy, *graw;
    cudaGetSymbolAddress((void**)&gq,   g_q);
    cudaGetSymbolAddress((void**)&gk,   g_k);
    cudaGetSymbolAddress((void**)&gv,   g_v);
    cudaGetSymbolAddress((void**)&gy,   g_y);
    cudaGetSymbolAddress((void**)&graw, g_raw);

    // Where the normalized attention lives: the harness out buffer if it has
    // room for (y, att); otherwise normalize in-place in the scratch.
    float* att = ((size_t)out_size >= Y_SIZE + ATT_SIZE) ? (out + Y_SIZE) : graw;

    dim3 thr(256);

    // 1) Projections: q/k/v = X @ W^T   (M=4096, N=1024, K per weight)
    dim3 gProj(DIM / 64, BT / 64);
    sgemm_xwT<<<gProj, thr>>>(Q, Wq, gq, BT, DIM, DIM);
    sgemm_xwT<<<gProj, thr>>>(K, Wk, gk, BT, DIM, DIM);
    sgemm_xwT<<<gProj, thr>>>(V, Wv, gv, BT, DIM, DIM);

    // 2) Raw causal scores
    dim3 gScore(T / 64, T / 64, B * H);
    scores_kernel<<<gScore, thr>>>(graw);

    // 3) Row softmax -> att (zeros written above the diagonal)
    softmax_kernel<<<(unsigned)(B * H * T), thr>>>(graw, att);

    // 4) y = att @ v
    dim3 gAV(1, T / 64, B * H);
    av_kernel<<<gAV, thr>>>(att);

    // 5) out = y @ Wo^T
    sgemm_xwT<<<gProj, thr>>>(gy, Wo, out, BT, DIM, DIM);
}

// round 2
// speedup vs baseline: 1.1382x; 1.1382x over previous
#include <cuda_runtime.h>
#include <cstddef>

// Problem constants
constexpr int B   = 2;
constexpr int T   = 2048;
constexpr int DIM = 1024;
constexpr int H   = 16;
constexpr int HD  = 64;           // DIM / H
constexpr int BT  = B * T;        // 4096
constexpr float SCALE = 0.03125f; // 1/sqrt(1024)

constexpr size_t Y_SIZE   = (size_t)BT * DIM;              // 4,194,304
constexpr size_t ATT_SIZE = (size_t)B * H * T * T;         // 134,217,728

// Scratch (allocation-free rule: __device__ globals)
__device__ float g_q[BT * DIM];
__device__ float g_k[BT * DIM];
__device__ float g_v[BT * DIM];
__device__ float g_y[BT * DIM];
__device__ float g_raw[ATT_SIZE];   // raw (scaled) attention scores

// ---------------------------------------------------------------------------
// 128x128x16 fp32 GEMM: C[M,N] = A[M,K] @ W[N,K]^T   (torch Linear)
// 256 threads, 8x8 per thread. M,N multiples of 128; K multiple of 16.
// ---------------------------------------------------------------------------
__global__ __launch_bounds__(256, 2)
void sgemm_xwT_128(const float* __restrict__ A, const float* __restrict__ W,
                   float* __restrict__ C, int M, int N, int K) {
    __shared__ float As[16][128];
    __shared__ float Bs[16][128];
    const int tid = threadIdx.x;
    const int m0  = blockIdx.y * 128;
    const int n0  = blockIdx.x * 128;
    const int tx  = tid & 15;     // 0..15 -> 8 cols each
    const int ty  = tid >> 4;     // 0..15 -> 8 rows each
    float c[8][8] = {};

    for (int k0 = 0; k0 < K; k0 += 16) {
#pragma unroll
        for (int i = 0; i < 2; ++i) {
            const int idx  = tid * 2 + i;     // 0..511
            const int row  = idx >> 2;        // 0..127
            const int col4 = (idx & 3) * 4;   // 0,4,8,12
            float4 a = *(const float4*)(A + (size_t)(m0 + row) * K + k0 + col4);
            As[col4 + 0][row] = a.x; As[col4 + 1][row] = a.y;
            As[col4 + 2][row] = a.z; As[col4 + 3][row] = a.w;
            float4 w = *(const float4*)(W + (size_t)(n0 + row) * K + k0 + col4);
            Bs[col4 + 0][row] = w.x; Bs[col4 + 1][row] = w.y;
            Bs[col4 + 2][row] = w.z; Bs[col4 + 3][row] = w.w;
        }
        __syncthreads();
#pragma unroll
        for (int k = 0; k < 16; ++k) {
            float a[8], b[8];
            *(float4*)(a)     = *(const float4*)&As[k][ty * 8];
            *(float4*)(a + 4) = *(const float4*)&As[k][ty * 8 + 4];
            *(float4*)(b)     = *(const float4*)&Bs[k][tx * 8];
            *(float4*)(b + 4) = *(const float4*)&Bs[k][tx * 8 + 4];
#pragma unroll
            for (int i = 0; i < 8; ++i)
#pragma unroll
                for (int j = 0; j < 8; ++j)
                    c[i][j] = fmaf(a[i], b[j], c[i][j]);
        }
        __syncthreads();
    }
#pragma unroll
    for (int i = 0; i < 8; ++i) {
        float* crow = C + (size_t)(m0 + ty * 8 + i) * N + n0 + tx * 8;
        *(float4*)(crow)     = make_float4(c[i][0], c[i][1], c[i][2], c[i][3]);
        *(float4*)(crow + 4) = make_float4(c[i][4], c[i][5], c[i][6], c[i][7]);
    }
}

// ---------------------------------------------------------------------------
// Raw scores: raw[bh,i,j] = SCALE * dot(q[b,h,i,:], k[b,h,j,:]).
// 128x128 tiles, skips tiles fully above the diagonal.
// ---------------------------------------------------------------------------
__global__ __launch_bounds__(256, 2)
void scores_kernel(float* __restrict__ raw) {
    const int bh = blockIdx.z;
    const int b  = bh >> 4;
    const int h  = bh & 15;
    const int i0 = blockIdx.y * 128;
    const int j0 = blockIdx.x * 128;
    if (j0 > i0) return;   // 128-aligned: j0 > i0 means fully masked

    const float* qb = g_q + (size_t)b * T * DIM + h * HD;
    const float* kb = g_k + (size_t)b * T * DIM + h * HD;

    __shared__ float As[16][128];
    __shared__ float Bs[16][128];
    const int tid = threadIdx.x;
    const int tx  = tid & 15;
    const int ty  = tid >> 4;
    float c[8][8] = {};

    for (int k0 = 0; k0 < HD; k0 += 16) {
#pragma unroll
        for (int i = 0; i < 2; ++i) {
            const int idx  = tid * 2 + i;
            const int row  = idx >> 2;
            const int col4 = (idx & 3) * 4;
            float4 a = *(const float4*)(qb + (size_t)(i0 + row) * DIM + k0 + col4);
            As[col4 + 0][row] = a.x; As[col4 + 1][row] = a.y;
            As[col4 + 2][row] = a.z; As[col4 + 3][row] = a.w;
            float4 w = *(const float4*)(kb + (size_t)(j0 + row) * DIM + k0 + col4);
            Bs[col4 + 0][row] = w.x; Bs[col4 + 1][row] = w.y;
            Bs[col4 + 2][row] = w.z; Bs[col4 + 3][row] = w.w;
        }
        __syncthreads();
#pragma unroll
        for (int k = 0; k < 16; ++k) {
            float a[8], b8[8];
            *(float4*)(a)      = *(const float4*)&As[k][ty * 8];
            *(float4*)(a + 4)  = *(const float4*)&As[k][ty * 8 + 4];
            *(float4*)(b8)     = *(const float4*)&Bs[k][tx * 8];
            *(float4*)(b8 + 4) = *(const float4*)&Bs[k][tx * 8 + 4];
#pragma unroll
            for (int i = 0; i < 8; ++i)
#pragma unroll
                for (int j = 0; j < 8; ++j)
                    c[i][j] = fmaf(a[i], b8[j], c[i][j]);
        }
        __syncthreads();
    }
    float* out = raw + (size_t)bh * T * T;
#pragma unroll
    for (int i = 0; i < 8; ++i) {
        float* crow = out + (size_t)(i0 + ty * 8 + i) * T + j0 + tx * 8;
        *(float4*)(crow)     = make_float4(c[i][0] * SCALE, c[i][1] * SCALE,
                                           c[i][2] * SCALE, c[i][3] * SCALE);
        *(float4*)(crow + 4) = make_float4(c[i][4] * SCALE, c[i][5] * SCALE,
                                           c[i][6] * SCALE, c[i][7] * SCALE);
    }
}

// ---------------------------------------------------------------------------
// Row softmax with causal masking, single global read pass (row cached in smem).
// One block of 256 threads per (bh, i) row.
// ---------------------------------------------------------------------------
__global__ __launch_bounds__(256)
void softmax_kernel(const float* __restrict__ raw, float* __restrict__ att) {
    const size_t row = blockIdx.x;          // 0 .. B*H*T-1
    const int i = (int)(row & (T - 1));     // row % T
    const float* r = raw + row * (size_t)T;
    float*       o = att + row * (size_t)T;
    const int n = i + 1;
    const int tid = threadIdx.x;

    __shared__ float s[T];       // 8 KB row cache
    __shared__ float red[256];

    float mx = -1e30f;
    for (int j = tid; j < n; j += 256) {
        float v = r[j];
        s[j] = v;
        mx = fmaxf(mx, v);
    }
    red[tid] = mx; __syncthreads();
#pragma unroll
    for (int st = 128; st > 0; st >>= 1) {
        if (tid < st) red[tid] = fmaxf(red[tid], red[tid + st]);
        __syncthreads();
    }
    mx = red[0]; __syncthreads();

    float sum = 0.f;
    for (int j = tid; j < n; j += 256) {
        float e = __expf(s[j] - mx);
        s[j] = e;
        sum += e;
    }
    red[tid] = sum; __syncthreads();
#pragma unroll
    for (int st = 128; st > 0; st >>= 1) {
        if (tid < st) red[tid] += red[tid + st];
        __syncthreads();
    }
    const float inv = 1.f / red[0];

    for (int j = tid; j < T; j += 256)
        o[j] = (j < n) ? s[j] * inv : 0.f;
}

// ---------------------------------------------------------------------------
// y[b,h,i,d] = sum_j att[bh,i,j] * v[b,h,j,d].  128x64 tile, 8x4 per thread.
// Skips j-tiles beyond the causal boundary (att there is exactly 0).
// ---------------------------------------------------------------------------
__global__ __launch_bounds__(256, 2)
void av_kernel(const float* __restrict__ att) {
    const int bh = blockIdx.z;
    const int b  = bh >> 4;
    const int h  = bh & 15;
    const int i0 = blockIdx.y * 128;

    const float* arow = att + (size_t)bh * T * T;
    const float* vb   = g_v + (size_t)b * T * DIM + h * HD;
    float*       yb   = g_y + (size_t)b * T * DIM + h * HD;

    __shared__ float As[16][128];   // As[j][i]  (att tile, transposed)
    __shared__ float Bs[16][64];    // Bs[j][d]  (v tile, natural)
    const int tid = threadIdx.x;
    const int tx  = tid & 15;       // 0..15 -> 4 cols each
    const int ty  = tid >> 4;       // 0..15 -> 8 rows each
    float c[8][4] = {};

    const int kmax = i0 + 128;      // j <= i <= i0+127
    for (int k0 = 0; k0 < kmax; k0 += 16) {
#pragma unroll
        for (int i = 0; i < 2; ++i) {
            const int idx  = tid * 2 + i;
            const int row  = idx >> 2;
            const int col4 = (idx & 3) * 4;
            float4 a = *(const float4*)(arow + (size_t)(i0 + row) * T + k0 + col4);
            As[col4 + 0][row] = a.x; As[col4 + 1][row] = a.y;
            As[col4 + 2][row] = a.z; As[col4 + 3][row] = a.w;
        }
        {
            const int jr  = tid >> 4;         // 0..15
            const int dc4 = (tid & 15) * 4;   // 0..60
            float4 v = *(const float4*)(vb + (size_t)(k0 + jr) * DIM + dc4);
            *(float4*)&Bs[jr][dc4] = v;
        }
        __syncthreads();
#pragma unroll
        for (int k = 0; k < 16; ++k) {
            float a[8], b4[4];
            *(float4*)(a)     = *(const float4*)&As[k][ty * 8];
            *(float4*)(a + 4) = *(const float4*)&As[k][ty * 8 + 4];
            *(float4*)(b4)    = *(const float4*)&Bs[k][tx * 4];
#pragma unroll
            for (int i = 0; i < 8; ++i)
#pragma unroll
                for (int j = 0; j < 4; ++j)
                    c[i][j] = fmaf(a[i], b4[j], c[i][j]);
        }
        __syncthreads();
    }
#pragma unroll
    for (int i = 0; i < 8; ++i) {
        float* crow = yb + (size_t)(i0 + ty * 8 + i) * DIM + tx * 4;
        *(float4*)crow = make_float4(c[i][0], c[i][1], c[i][2], c[i][3]);
    }
}

// ---------------------------------------------------------------------------
extern "C" void kernel_launch(void* const* d_in, const int* in_sizes, int n_in,
                              void* d_out, int out_size) {
    const float* Q  = (const float*)d_in[0];
    const float* K  = (const float*)d_in[1];
    const float* V  = (const float*)d_in[2];
    const float* Wq = (const float*)d_in[3];
    const float* Wk = (const float*)d_in[4];
    const float* Wv = (const float*)d_in[5];
    const float* Wo = (const float*)d_in[6];
    float* out = (float*)d_out;

    float *gq, *gk, *gv, *gy, *graw;
    cudaGetSymbolAddress((void**)&gq,   g_q);
    cudaGetSymbolAddress((void**)&gk,   g_k);
    cudaGetSymbolAddress((void**)&gv,   g_v);
    cudaGetSymbolAddress((void**)&gy,   g_y);
    cudaGetSymbolAddress((void**)&graw, g_raw);

    float* att = ((size_t)out_size >= Y_SIZE + ATT_SIZE) ? (out + Y_SIZE) : graw;

    dim3 thr(256);

    // 1) Projections: q/k/v = X @ W^T   (M=4096, N=1024, K=1024)
    dim3 gProj(DIM / 128, BT / 128);
    sgemm_xwT_128<<<gProj, thr>>>(Q, Wq, gq, BT, DIM, DIM);
    sgemm_xwT_128<<<gProj, thr>>>(K, Wk, gk, BT, DIM, DIM);
    sgemm_xwT_128<<<gProj, thr>>>(V, Wv, gv, BT, DIM, DIM);

    // 2) Raw causal scores (128x128 tiles, upper tiles skipped)
    dim3 gScore(T / 128, T / 128, B * H);
    scores_kernel<<<gScore, thr>>>(graw);

    // 3) Row softmax -> att (zeros written above the diagonal)
    softmax_kernel<<<(unsigned)(B * H * T), thr>>>(graw, att);

    // 4) y = att @ v
    dim3 gAV(1, T / 128, B * H);
    av_kernel<<<gAV, thr>>>(att);

    // 5) out = y @ Wo^T
    sgemm_xwT_128<<<gProj, thr>>>(gy, Wo, out, BT, DIM, DIM);
}

// round 8
// speedup vs baseline: 1.6575x; 1.4563x over previous
#include <cuda_runtime.h>
#include <cuda_bf16.h>
#include <cstdint>
#include <cstddef>

// Problem constants
constexpr int B   = 2;
constexpr int T   = 2048;
constexpr int DIM = 1024;
constexpr int H   = 16;
constexpr int HD  = 64;
constexpr int BT  = B * T;        // 4096
constexpr float SCALE = 0.03125f; // 1/sqrt(1024)

constexpr size_t Y_SIZE   = (size_t)BT * DIM;
constexpr size_t ATT_SIZE = (size_t)B * H * T * T;

// Scratch (allocation-free rule: __device__ globals)
__device__ float g_q[BT * DIM];
__device__ float g_k[BT * DIM];
__device__ float g_v[BT * DIM];
__device__ float g_y[BT * DIM];
__device__ float g_raw[ATT_SIZE];

// ===========================================================================
// mma.sync helpers (standard PTX ISA — legal on plain sm_103 target)
// ===========================================================================
__device__ __forceinline__ uint32_t smem_u32(const void* p) {
    uint32_t a;
    asm("{ .reg .u64 t; cvta.to.shared.u64 t, %1; cvt.u32.u64 %0, t; }" : "=r"(a) : "l"(p));
    return a;
}
__device__ __forceinline__ void ldsm_x4(uint32_t& r0, uint32_t& r1, uint32_t& r2,
                                        uint32_t& r3, uint32_t addr) {
    asm volatile("ldmatrix.sync.aligned.m8n8.x4.shared.b16 {%0,%1,%2,%3}, [%4];"
                 : "=r"(r0), "=r"(r1), "=r"(r2), "=r"(r3) : "r"(addr));
}
__device__ __forceinline__ void ldsm_x2(uint32_t& r0, uint32_t& r1, uint32_t addr) {
    asm volatile("ldmatrix.sync.aligned.m8n8.x2.shared.b16 {%0,%1}, [%2];"
                 : "=r"(r0), "=r"(r1) : "r"(addr));
}
__device__ __forceinline__ void mma_bf16(float* c, const uint32_t* a, const uint32_t* b) {
    asm volatile(
        "mma.sync.aligned.m16n8k16.row.col.f32.bf16.bf16.f32 "
        "{%0,%1,%2,%3}, {%4,%5,%6,%7}, {%8,%9}, {%0,%1,%2,%3};"
        : "+f"(c[0]), "+f"(c[1]), "+f"(c[2]), "+f"(c[3])
        : "r"(a[0]), "r"(a[1]), "r"(a[2]), "r"(a[3]), "r"(b[0]), "r"(b[1]));
}
// Split fp32 into bf16 hi + lo (x ~= hi + lo, ~16 mantissa bits kept)
__device__ __forceinline__ void split4(float4 v, uint2& hi, uint2& lo) {
    __nv_bfloat16 h0 = __float2bfloat16_rn(v.x);
    __nv_bfloat16 h1 = __float2bfloat16_rn(v.y);
    __nv_bfloat16 h2 = __float2bfloat16_rn(v.z);
    __nv_bfloat16 h3 = __float2bfloat16_rn(v.w);
    __nv_bfloat16 l0 = __float2bfloat16_rn(v.x - __bfloat162float(h0));
    __nv_bfloat16 l1 = __float2bfloat16_rn(v.y - __bfloat162float(h1));
    __nv_bfloat16 l2 = __float2bfloat16_rn(v.z - __bfloat162float(h2));
    __nv_bfloat16 l3 = __float2bfloat16_rn(v.w - __bfloat162float(h3));
    __nv_bfloat162 hA = {h0, h1}, hB = {h2, h3}, lA = {l0, l1}, lB = {l2, l3};
    hi = make_uint2(*(uint32_t*)&hA, *(uint32_t*)&hB);
    lo = make_uint2(*(uint32_t*)&lA, *(uint32_t*)&lB);
}

// ===========================================================================
// bf16x3 split GEMM: C[4096,1024] = A[4096,1024] @ W[1024,1024]^T
// 128x128 CTA tile, 8 warps (2x4), warp tile 64x32, K-chunk 32.
// ===========================================================================
constexpr int KDIM = 1024;
constexpr int NDIM = 1024;
constexpr int KCH  = 32;                  // K per chunk
constexpr int NCH  = KDIM / KCH;          // 32 chunks
constexpr int SPAD = 40;                  // smem row stride (bf16 elems)

__global__ __launch_bounds__(256, 1)
void gemm_bf16x3(const float* __restrict__ A, const float* __restrict__ W,
                 float* __restrict__ C) {
    __shared__ __nv_bfloat16 sAhi[128][SPAD];
    __shared__ __nv_bfloat16 sAlo[128][SPAD];
    __shared__ __nv_bfloat16 sWhi[128][SPAD];
    __shared__ __nv_bfloat16 sWlo[128][SPAD];

    const int tid  = threadIdx.x;
    const int wid  = tid >> 5;
    const int lane = tid & 31;
    const int warp_m = wid >> 2;          // 0..1 -> 64 rows each
    const int warp_n = wid & 3;           // 0..3 -> 32 cols each
    const int m0 = blockIdx.y * 128;
    const int n0 = blockIdx.x * 128;

    float c[4][4][4] = {};                // [m-tile][n-tile][frag]
    float4 pa[4], pw[4];

    // Prefetch chunk 0
#pragma unroll
    for (int i = 0; i < 4; ++i) {
        const int idx = tid + i * 256;
        const int row = idx >> 3, c4 = (idx & 7) * 4;
        pa[i] = *(const float4*)(A + (size_t)(m0 + row) * KDIM + c4);
        pw[i] = *(const float4*)(W + (size_t)(n0 + row) * KDIM + c4);
    }

    for (int ch = 0; ch < NCH; ++ch) {
        // Convert current chunk into smem
#pragma unroll
        for (int i = 0; i < 4; ++i) {
            const int idx = tid + i * 256;
            const int row = idx >> 3, c4 = (idx & 7) * 4;
            uint2 hi, lo;
            split4(pa[i], hi, lo);
            *(uint2*)&sAhi[row][c4] = hi;
            *(uint2*)&sAlo[row][c4] = lo;
            split4(pw[i], hi, lo);
            *(uint2*)&sWhi[row][c4] = hi;
            *(uint2*)&sWlo[row][c4] = lo;
        }
        __syncthreads();

        // Prefetch next chunk (overlaps MMA below)
        if (ch + 1 < NCH) {
            const int k0n = (ch + 1) * KCH;
#pragma unroll
            for (int i = 0; i < 4; ++i) {
                const int idx = tid + i * 256;
                const int row = idx >> 3, c4 = (idx & 7) * 4;
                pa[i] = *(const float4*)(A + (size_t)(m0 + row) * KDIM + k0n + c4);
                pw[i] = *(const float4*)(W + (size_t)(n0 + row) * KDIM + k0n + c4);
            }
        }

        // MMA: 2 k-steps of 16
#pragma unroll
        for (int ks = 0; ks < 2; ++ks) {
            const int kc = ks * 16;
            uint32_t ah[4][4], al[4][4], bh[4][2], bl[4][2];
#pragma unroll
            for (int mt = 0; mt < 4; ++mt) {
                const int r   = warp_m * 64 + mt * 16 + (lane & 15);
                const int col = kc + ((lane >> 4) << 3);
                ldsm_x4(ah[mt][0], ah[mt][1], ah[mt][2], ah[mt][3],
                        smem_u32(&sAhi[r][col]));
                ldsm_x4(al[mt][0], al[mt][1], al[mt][2], al[mt][3],
                        smem_u32(&sAlo[r][col]));
            }
#pragma unroll
            for (int nt = 0; nt < 4; ++nt) {
                const int t   = lane & 15;
                const int r   = warp_n * 32 + nt * 8 + (t & 7);
                const int col = kc + ((t >> 3) << 3);
                ldsm_x2(bh[nt][0], bh[nt][1], smem_u32(&sWhi[r][col]));
                ldsm_x2(bl[nt][0], bl[nt][1], smem_u32(&sWlo[r][col]));
            }
#pragma unroll
            for (int mt = 0; mt < 4; ++mt)
#pragma unroll
                for (int nt = 0; nt < 4; ++nt) {
                    mma_bf16(c[mt][nt], ah[mt], bh[nt]);
                    mma_bf16(c[mt][nt], ah[mt], bl[nt]);
                    mma_bf16(c[mt][nt], al[mt], bh[nt]);
                }
        }
        __syncthreads();
    }

    // Epilogue
#pragma unroll
    for (int mt = 0; mt < 4; ++mt) {
        const int r0 = m0 + warp_m * 64 + mt * 16 + (lane >> 2);
#pragma unroll
        for (int nt = 0; nt < 4; ++nt) {
            const int cc = n0 + warp_n * 32 + nt * 8 + (lane & 3) * 2;
            *(float2*)(C + (size_t)r0 * NDIM + cc)       = make_float2(c[mt][nt][0], c[mt][nt][1]);
            *(float2*)(C + (size_t)(r0 + 8) * NDIM + cc) = make_float2(c[mt][nt][2], c[mt][nt][3]);
        }
    }
}

// ===========================================================================
// fp32 scores / softmax / AV (unchanged — round-2 proven)
// ===========================================================================
__global__ __launch_bounds__(256, 2)
void scores_kernel(float* __restrict__ raw) {
    const int bh = blockIdx.z;
    const int b  = bh >> 4;
    const int h  = bh & 15;
    const int i0 = blockIdx.y * 128;
    const int j0 = blockIdx.x * 128;
    if (j0 > i0) return;

    const float* qb = g_q + (size_t)b * T * DIM + h * HD;
    const float* kb = g_k + (size_t)b * T * DIM + h * HD;

    __shared__ float As[16][128];
    __shared__ float Bs[16][128];
    const int tid = threadIdx.x;
    const int tx  = tid & 15;
    const int ty  = tid >> 4;
    float c[8][8] = {};

    for (int k0 = 0; k0 < HD; k0 += 16) {
#pragma unroll
        for (int i = 0; i < 2; ++i) {
            const int idx  = tid * 2 + i;
            const int row  = idx >> 2;
            const int col4 = (idx & 3) * 4;
            float4 a = *(const float4*)(qb + (size_t)(i0 + row) * DIM + k0 + col4);
            As[col4 + 0][row] = a.x; As[col4 + 1][row] = a.y;
            As[col4 + 2][row] = a.z; As[col4 + 3][row] = a.w;
            float4 w = *(const float4*)(kb + (size_t)(j0 + row) * DIM + k0 + col4);
            Bs[col4 + 0][row] = w.x; Bs[col4 + 1][row] = w.y;
            Bs[col4 + 2][row] = w.z; Bs[col4 + 3][row] = w.w;
        }
        __syncthreads();
#pragma unroll
        for (int k = 0; k < 16; ++k) {
            float a[8], b8[8];
            *(float4*)(a)      = *(const float4*)&As[k][ty * 8];
            *(float4*)(a + 4)  = *(const float4*)&As[k][ty * 8 + 4];
            *(float4*)(b8)     = *(const float4*)&Bs[k][tx * 8];
            *(float4*)(b8 + 4) = *(const float4*)&Bs[k][tx * 8 + 4];
#pragma unroll
            for (int i = 0; i < 8; ++i)
#pragma unroll
                for (int j = 0; j < 8; ++j)
                    c[i][j] = fmaf(a[i], b8[j], c[i][j]);
        }
        __syncthreads();
    }
    float* out = raw + (size_t)bh * T * T;
#pragma unroll
    for (int i = 0; i < 8; ++i) {
        float* crow = out + (size_t)(i0 + ty * 8 + i) * T + j0 + tx * 8;
        *(float4*)(crow)     = make_float4(c[i][0] * SCALE, c[i][1] * SCALE,
                                           c[i][2] * SCALE, c[i][3] * SCALE);
        *(float4*)(crow + 4) = make_float4(c[i][4] * SCALE, c[i][5] * SCALE,
                                           c[i][6] * SCALE, c[i][7] * SCALE);
    }
}

__global__ __launch_bounds__(256)
void softmax_kernel(const float* __restrict__ raw, float* __restrict__ att) {
    const size_t row = blockIdx.x;
    const int i = (int)(row & (T - 1));
    const float* r = raw + row * (size_t)T;
    float*       o = att + row * (size_t)T;
    const int n = i + 1;
    const int tid = threadIdx.x;

    __shared__ float s[T];
    __shared__ float red[256];

    float mx = -1e30f;
    for (int j = tid; j < n; j += 256) {
        float v = r[j];
        s[j] = v;
        mx = fmaxf(mx, v);
    }
    red[tid] = mx; __syncthreads();
#pragma unroll
    for (int st = 128; st > 0; st >>= 1) {
        if (tid < st) red[tid] = fmaxf(red[tid], red[tid + st]);
        __syncthreads();
    }
    mx = red[0]; __syncthreads();

    float sum = 0.f;
    for (int j = tid; j < n; j += 256) {
        float e = __expf(s[j] - mx);
        s[j] = e;
        sum += e;
    }
    red[tid] = sum; __syncthreads();
#pragma unroll
    for (int st = 128; st > 0; st >>= 1) {
        if (tid < st) red[tid] += red[tid + st];
        __syncthreads();
    }
    const float inv = 1.f / red[0];

    for (int j = tid; j < T; j += 256)
        o[j] = (j < n) ? s[j] * inv : 0.f;
}

__global__ __launch_bounds__(256, 2)
void av_kernel(const float* __restrict__ att) {
    const int bh = blockIdx.z;
    const int b  = bh >> 4;
    const int h  = bh & 15;
    const int i0 = blockIdx.y * 128;

    const float* arow = att + (size_t)bh * T * T;
    const float* vb   = g_v + (size_t)b * T * DIM + h * HD;
    float*       yb   = g_y + (size_t)b * T * DIM + h * HD;

    __shared__ float As[16][128];
    __shared__ float Bs[16][64];
    const int tid = threadIdx.x;
    const int tx  = tid & 15;
    const int ty  = tid >> 4;
    float c[8][4] = {};

    const int kmax = i0 + 128;
    for (int k0 = 0; k0 < kmax; k0 += 16) {
#pragma unroll
        for (int i = 0; i < 2; ++i) {
            const int idx  = tid * 2 + i;
            const int row  = idx >> 2;
            const int col4 = (idx & 3) * 4;
            float4 a = *(const float4*)(arow + (size_t)(i0 + row) * T + k0 + col4);
            As[col4 + 0][row] = a.x; As[col4 + 1][row] = a.y;
            As[col4 + 2][row] = a.z; As[col4 + 3][row] = a.w;
        }
        {
            const int jr  = tid >> 4;
            const int dc4 = (tid & 15) * 4;
            float4 v = *(const float4*)(vb + (size_t)(k0 + jr) * DIM + dc4);
            *(float4*)&Bs[jr][dc4] = v;
        }
        __syncthreads();
#pragma unroll
        for (int k = 0; k < 16; ++k) {
            float a[8], b4[4];
            *(float4*)(a)     = *(const float4*)&As[k][ty * 8];
            *(float4*)(a + 4) = *(const float4*)&As[k][ty * 8 + 4];
            *(float4*)(b4)    = *(const float4*)&Bs[k][tx * 4];
#pragma unroll
            for (int i = 0; i < 8; ++i)
#pragma unroll
                for (int j = 0; j < 4; ++j)
                    c[i][j] = fmaf(a[i], b4[j], c[i][j]);
        }
        __syncthreads();
    }
#pragma unroll
    for (int i = 0; i < 8; ++i) {
        float* crow = yb + (size_t)(i0 + ty * 8 + i) * DIM + tx * 4;
        *(float4*)crow = make_float4(c[i][0], c[i][1], c[i][2], c[i][3]);
    }
}

// ===========================================================================
extern "C" void kernel_launch(void* const* d_in, const int* in_sizes, int n_in,
                              void* d_out, int out_size) {
    const float* Q  = (const float*)d_in[0];
    const float* K  = (const float*)d_in[1];
    const float* V  = (const float*)d_in[2];
    const float* Wq = (const float*)d_in[3];
    const float* Wk = (const float*)d_in[4];
    const float* Wv = (const float*)d_in[5];
    const float* Wo = (const float*)d_in[6];
    float* out = (float*)d_out;

    float *gq, *gk, *gv, *gy, *graw;
    cudaGetSymbolAddress((void**)&gq,   g_q);
    cudaGetSymbolAddress((void**)&gk,   g_k);
    cudaGetSymbolAddress((void**)&gv,   g_v);
    cudaGetSymbolAddress((void**)&gy,   g_y);
    cudaGetSymbolAddress((void**)&graw, g_raw);

    float* att = ((size_t)out_size >= Y_SIZE + ATT_SIZE) ? (out + Y_SIZE) : graw;

    dim3 thr(256);
    dim3 gGemm(NDIM / 128, BT / 128);   // (8, 32)

    // 1) Projections (tensor cores via mma.sync, bf16x3 split)
    gemm_bf16x3<<<gGemm, thr>>>(Q, Wq, gq);
    gemm_bf16x3<<<gGemm, thr>>>(K, Wk, gk);
    gemm_bf16x3<<<gGemm, thr>>>(V, Wv, gv);

    // 2) Raw causal scores
    dim3 gScore(T / 128, T / 128, B * H);
    scores_kernel<<<gScore, thr>>>(graw);

    // 3) Row softmax -> att
    softmax_kernel<<<(unsigned)(B * H * T), thr>>>(graw, att);

    // 4) y = att @ v
    dim3 gAV(1, T / 128, B * H);
    av_kernel<<<gAV, thr>>>(att);

    // 5) out = y @ Wo^T (tensor cores)
    gemm_bf16x3<<<gGemm, thr>>>(gy, Wo, out);
}

// round 9
// speedup vs baseline: 2.0534x; 1.2388x over previous
#include <cuda_runtime.h>
#include <cuda_bf16.h>
#include <cstdint>
#include <cstddef>

// Problem constants
constexpr int B   = 2;
constexpr int T   = 2048;
constexpr int DIM = 1024;
constexpr int H   = 16;
constexpr int HD  = 64;
constexpr int BT  = B * T;        // 4096
constexpr float SCALE = 0.03125f; // 1/sqrt(1024)

constexpr size_t Y_SIZE   = (size_t)BT * DIM;
constexpr size_t ATT_SIZE = (size_t)B * H * T * T;

// Scratch (allocation-free rule: __device__ globals)
__device__ __nv_bfloat16 g_qhi[BT * DIM];
__device__ __nv_bfloat16 g_qlo[BT * DIM];
__device__ __nv_bfloat16 g_khi[BT * DIM];
__device__ __nv_bfloat16 g_klo[BT * DIM];
__device__ __nv_bfloat16 g_vhi[BT * DIM];
__device__ __nv_bfloat16 g_vlo[BT * DIM];
__device__ float g_y[BT * DIM];
__device__ float g_raw[ATT_SIZE];

// ===========================================================================
// mma.sync helpers (standard PTX ISA — legal on plain sm_103 target)
// ===========================================================================
__device__ __forceinline__ uint32_t smem_u32(const void* p) {
    uint32_t a;
    asm("{ .reg .u64 t; cvta.to.shared.u64 t, %1; cvt.u32.u64 %0, t; }" : "=r"(a) : "l"(p));
    return a;
}
__device__ __forceinline__ void ldsm_x4(uint32_t& r0, uint32_t& r1, uint32_t& r2,
                                        uint32_t& r3, uint32_t addr) {
    asm volatile("ldmatrix.sync.aligned.m8n8.x4.shared.b16 {%0,%1,%2,%3}, [%4];"
                 : "=r"(r0), "=r"(r1), "=r"(r2), "=r"(r3) : "r"(addr));
}
__device__ __forceinline__ void ldsm_x2(uint32_t& r0, uint32_t& r1, uint32_t addr) {
    asm volatile("ldmatrix.sync.aligned.m8n8.x2.shared.b16 {%0,%1}, [%2];"
                 : "=r"(r0), "=r"(r1) : "r"(addr));
}
__device__ __forceinline__ void ldsm_x2_t(uint32_t& r0, uint32_t& r1, uint32_t addr) {
    asm volatile("ldmatrix.sync.aligned.m8n8.x2.trans.shared.b16 {%0,%1}, [%2];"
                 : "=r"(r0), "=r"(r1) : "r"(addr));
}
__device__ __forceinline__ void mma_bf16(float* c, const uint32_t* a, const uint32_t* b) {
    asm volatile(
        "mma.sync.aligned.m16n8k16.row.col.f32.bf16.bf16.f32 "
        "{%0,%1,%2,%3}, {%4,%5,%6,%7}, {%8,%9}, {%0,%1,%2,%3};"
        : "+f"(c[0]), "+f"(c[1]), "+f"(c[2]), "+f"(c[3])
        : "r"(a[0]), "r"(a[1]), "r"(a[2]), "r"(a[3]), "r"(b[0]), "r"(b[1]));
}
__device__ __forceinline__ void split4(float4 v, uint2& hi, uint2& lo) {
    __nv_bfloat16 h0 = __float2bfloat16_rn(v.x);
    __nv_bfloat16 h1 = __float2bfloat16_rn(v.y);
    __nv_bfloat16 h2 = __float2bfloat16_rn(v.z);
    __nv_bfloat16 h3 = __float2bfloat16_rn(v.w);
    __nv_bfloat16 l0 = __float2bfloat16_rn(v.x - __bfloat162float(h0));
    __nv_bfloat16 l1 = __float2bfloat16_rn(v.y - __bfloat162float(h1));
    __nv_bfloat16 l2 = __float2bfloat16_rn(v.z - __bfloat162float(h2));
    __nv_bfloat16 l3 = __float2bfloat16_rn(v.w - __bfloat162float(h3));
    __nv_bfloat162 hA = {h0, h1}, hB = {h2, h3}, lA = {l0, l1}, lB = {l2, l3};
    hi = make_uint2(*(uint32_t*)&hA, *(uint32_t*)&hB);
    lo = make_uint2(*(uint32_t*)&lA, *(uint32_t*)&lB);
}
__device__ __forceinline__ uint32_t pack_split2(float a, float b) {
    __nv_bfloat16 ha = __float2bfloat16_rn(a);
    __nv_bfloat16 hb = __float2bfloat16_rn(b);
    __nv_bfloat162 p = {ha, hb};
    return *(uint32_t*)&p;
}

// ===========================================================================
// bf16x3 split GEMM: C[4096,1024] = A[4096,1024] @ W[1024,1024]^T
// 128x128 CTA tile, 8 warps (2x4), warp tile 64x32, K-chunk 32.
// SPLIT=true: write C as bf16 hi/lo pair buffers. SPLIT=false: fp32 C.
// ===========================================================================
constexpr int KDIM = 1024;
constexpr int NDIM = 1024;
constexpr int KCH  = 32;
constexpr int NCHG = KDIM / KCH;
constexpr int SPAD = 40;

template <bool SPLIT>
__global__ __launch_bounds__(256, 1)
void gemm_bf16x3(const float* __restrict__ A, const float* __restrict__ W,
                 float* __restrict__ C,
                 __nv_bfloat16* __restrict__ Chi, __nv_bfloat16* __restrict__ Clo) {
    __shared__ __nv_bfloat16 sAhi[128][SPAD];
    __shared__ __nv_bfloat16 sAlo[128][SPAD];
    __shared__ __nv_bfloat16 sWhi[128][SPAD];
    __shared__ __nv_bfloat16 sWlo[128][SPAD];

    const int tid  = threadIdx.x;
    const int wid  = tid >> 5;
    const int lane = tid & 31;
    const int warp_m = wid >> 2;
    const int warp_n = wid & 3;
    const int m0 = blockIdx.y * 128;
    const int n0 = blockIdx.x * 128;

    float c[4][4][4] = {};
    float4 pa[4], pw[4];

#pragma unroll
    for (int i = 0; i < 4; ++i) {
        const int idx = tid + i * 256;
        const int row = idx >> 3, c4 = (idx & 7) * 4;
        pa[i] = *(const float4*)(A + (size_t)(m0 + row) * KDIM + c4);
        pw[i] = *(const float4*)(W + (size_t)(n0 + row) * KDIM + c4);
    }

    for (int ch = 0; ch < NCHG; ++ch) {
#pragma unroll
        for (int i = 0; i < 4; ++i) {
            const int idx = tid + i * 256;
            const int row = idx >> 3, c4 = (idx & 7) * 4;
            uint2 hi, lo;
            split4(pa[i], hi, lo);
            *(uint2*)&sAhi[row][c4] = hi;
            *(uint2*)&sAlo[row][c4] = lo;
            split4(pw[i], hi, lo);
            *(uint2*)&sWhi[row][c4] = hi;
            *(uint2*)&sWlo[row][c4] = lo;
        }
        __syncthreads();

        if (ch + 1 < NCHG) {
            const int k0n = (ch + 1) * KCH;
#pragma unroll
            for (int i = 0; i < 4; ++i) {
                const int idx = tid + i * 256;
                const int row = idx >> 3, c4 = (idx & 7) * 4;
                pa[i] = *(const float4*)(A + (size_t)(m0 + row) * KDIM + k0n + c4);
                pw[i] = *(const float4*)(W + (size_t)(n0 + row) * KDIM + k0n + c4);
            }
        }

#pragma unroll
        for (int ks = 0; ks < 2; ++ks) {
            const int kc = ks * 16;
            uint32_t ah[4][4], al[4][4], bh[4][2], bl[4][2];
#pragma unroll
            for (int mt = 0; mt < 4; ++mt) {
                const int r   = warp_m * 64 + mt * 16 + (lane & 15);
                const int col = kc + ((lane >> 4) << 3);
                ldsm_x4(ah[mt][0], ah[mt][1], ah[mt][2], ah[mt][3],
                        smem_u32(&sAhi[r][col]));
                ldsm_x4(al[mt][0], al[mt][1], al[mt][2], al[mt][3],
                        smem_u32(&sAlo[r][col]));
            }
#pragma unroll
            for (int nt = 0; nt < 4; ++nt) {
                const int t   = lane & 15;
                const int r   = warp_n * 32 + nt * 8 + (t & 7);
                const int col = kc + ((t >> 3) << 3);
                ldsm_x2(bh[nt][0], bh[nt][1], smem_u32(&sWhi[r][col]));
                ldsm_x2(bl[nt][0], bl[nt][1], smem_u32(&sWlo[r][col]));
            }
#pragma unroll
            for (int mt = 0; mt < 4; ++mt)
#pragma unroll
                for (int nt = 0; nt < 4; ++nt) {
                    mma_bf16(c[mt][nt], ah[mt], bh[nt]);
                    mma_bf16(c[mt][nt], ah[mt], bl[nt]);
                    mma_bf16(c[mt][nt], al[mt], bh[nt]);
                }
        }
        __syncthreads();
    }

#pragma unroll
    for (int mt = 0; mt < 4; ++mt) {
        const int r0 = m0 + warp_m * 64 + mt * 16 + (lane >> 2);
#pragma unroll
        for (int nt = 0; nt < 4; ++nt) {
            const int cc = n0 + warp_n * 32 + nt * 8 + (lane & 3) * 2;
            if (SPLIT) {
#pragma unroll
                for (int rr = 0; rr < 2; ++rr) {
                    const size_t off = (size_t)(r0 + rr * 8) * NDIM + cc;
                    float v0 = c[mt][nt][rr * 2], v1 = c[mt][nt][rr * 2 + 1];
                    __nv_bfloat16 h0 = __float2bfloat16_rn(v0);
                    __nv_bfloat16 h1 = __float2bfloat16_rn(v1);
                    __nv_bfloat162 hp = {h0, h1};
                    __nv_bfloat162 lp = {__float2bfloat16_rn(v0 - __bfloat162float(h0)),
                                         __float2bfloat16_rn(v1 - __bfloat162float(h1))};
                    *(uint32_t*)(Chi + off) = *(uint32_t*)&hp;
                    *(uint32_t*)(Clo + off) = *(uint32_t*)&lp;
                }
            } else {
                *(float2*)(C + (size_t)r0 * NDIM + cc)       = make_float2(c[mt][nt][0], c[mt][nt][1]);
                *(float2*)(C + (size_t)(r0 + 8) * NDIM + cc) = make_float2(c[mt][nt][2], c[mt][nt][3]);
            }
        }
    }
}

// ===========================================================================
// Tensor-core scores: raw[bh,i,j] = SCALE * dot(q_i, k_j), bf16x3 split.
// 128x128 per CTA, K=64 loaded once (dynamic smem), causal tiles skipped.
// ===========================================================================
constexpr int SP64 = 72;                              // pad 64 -> 72 (144B rows)
constexpr int SCORES_SMEM = 4 * 128 * SP64 * 2;       // 73728 B

__global__ __launch_bounds__(256, 1)
void scores_mma(float* __restrict__ raw) {
    const int bh = blockIdx.z;
    const int b  = bh >> 4;
    const int h  = bh & 15;
    const int i0 = blockIdx.y * 128;
    const int j0 = blockIdx.x * 128;
    if (j0 > i0) return;

    extern __shared__ __nv_bfloat16 sm[];
    __nv_bfloat16* sQhi = sm;
    __nv_bfloat16* sQlo = sm + 128 * SP64;
    __nv_bfloat16* sKhi = sm + 2 * 128 * SP64;
    __nv_bfloat16* sKlo = sm + 3 * 128 * SP64;

    const int tid  = threadIdx.x;
    const int wid  = tid >> 5;
    const int lane = tid & 31;
    const int warp_m = wid >> 2;     // 2 x 64 rows
    const int warp_n = wid & 3;      // 4 x 32 cols

    const size_t qbase = ((size_t)b * T) * DIM + h * HD;

    // Load q/k tiles (hi+lo), 128x64 bf16 each: 1024 uint4 per array
#pragma unroll
    for (int i = 0; i < 4; ++i) {
        const int idx = tid + i * 256;       // 0..1023
        const int row = idx >> 3;            // 0..127
        const int c8  = (idx & 7) * 8;       // 0..56
        const size_t qoff = qbase + (size_t)(i0 + row) * DIM + c8;
        const size_t koff = qbase + (size_t)(j0 + row) * DIM + c8;
        *(uint4*)&sQhi[row * SP64 + c8] = *(const uint4*)(g_qhi + qoff);
        *(uint4*)&sQlo[row * SP64 + c8] = *(const uint4*)(g_qlo + qoff);
        *(uint4*)&sKhi[row * SP64 + c8] = *(const uint4*)(g_khi + koff);
        *(uint4*)&sKlo[row * SP64 + c8] = *(const uint4*)(g_klo + koff);
    }
    __syncthreads();

    float c[4][4][4] = {};
#pragma unroll
    for (int ks = 0; ks < 4; ++ks) {
        const int kc = ks * 16;
        uint32_t ah[4][4], al[4][4], bh[4][2], bl[4][2];
#pragma unroll
        for (int mt = 0; mt < 4; ++mt) {
            const int r   = warp_m * 64 + mt * 16 + (lane & 15);
            const int col = kc + ((lane >> 4) << 3);
            ldsm_x4(ah[mt][0], ah[mt][1], ah[mt][2], ah[mt][3],
                    smem_u32(&sQhi[r * SP64 + col]));
            ldsm_x4(al[mt][0], al[mt][1], al[mt][2], al[mt][3],
                    smem_u32(&sQlo[r * SP64 + col]));
        }
#pragma unroll
        for (int nt = 0; nt < 4; ++nt) {
            const int t   = lane & 15;
            const int r   = warp_n * 32 + nt * 8 + (t & 7);
            const int col = kc + ((t >> 3) << 3);
            ldsm_x2(bh[nt][0], bh[nt][1], smem_u32(&sKhi[r * SP64 + col]));
            ldsm_x2(bl[nt][0], bl[nt][1], smem_u32(&sKlo[r * SP64 + col]));
        }
#pragma unroll
        for (int mt = 0; mt < 4; ++mt)
#pragma unroll
            for (int nt = 0; nt < 4; ++nt) {
                mma_bf16(c[mt][nt], ah[mt], bh[nt]);
                mma_bf16(c[mt][nt], ah[mt], bl[nt]);
                mma_bf16(c[mt][nt], al[mt], bh[nt]);
            }
    }

    float* outp = raw + (size_t)bh * T * T;
#pragma unroll
    for (int mt = 0; mt < 4; ++mt) {
        const int r0 = i0 + warp_m * 64 + mt * 16 + (lane >> 2);
#pragma unroll
        for (int nt = 0; nt < 4; ++nt) {
            const int cc = j0 + warp_n * 32 + nt * 8 + (lane & 3) * 2;
            *(float2*)(outp + (size_t)r0 * T + cc) =
                make_float2(c[mt][nt][0] * SCALE, c[mt][nt][1] * SCALE);
            *(float2*)(outp + (size_t)(r0 + 8) * T + cc) =
                make_float2(c[mt][nt][2] * SCALE, c[mt][nt][3] * SCALE);
        }
    }
}

// ===========================================================================
// Row softmax (unchanged)
// ===========================================================================
__global__ __launch_bounds__(256)
void softmax_kernel(const float* __restrict__ raw, float* __restrict__ att) {
    const size_t row = blockIdx.x;
    const int i = (int)(row & (T - 1));
    const float* r = raw + row * (size_t)T;
    float*       o = att + row * (size_t)T;
    const int n = i + 1;
    const int tid = threadIdx.x;

    __shared__ float s[T];
    __shared__ float red[256];

    float mx = -1e30f;
    for (int j = tid; j < n; j += 256) {
        float v = r[j];
        s[j] = v;
        mx = fmaxf(mx, v);
    }
    red[tid] = mx; __syncthreads();
#pragma unroll
    for (int st = 128; st > 0; st >>= 1) {
        if (tid < st) red[tid] = fmaxf(red[tid], red[tid + st]);
        __syncthreads();
    }
    mx = red[0]; __syncthreads();

    float sum = 0.f;
    for (int j = tid; j < n; j += 256) {
        float e = __expf(s[j] - mx);
        s[j] = e;
        sum += e;
    }
    red[tid] = sum; __syncthreads();
#pragma unroll
    for (int st = 128; st > 0; st >>= 1) {
        if (tid < st) red[tid] += red[tid + st];
        __syncthreads();
    }
    const float inv = 1.f / red[0];

    for (int j = tid; j < T; j += 256)
        o[j] = (j < n) ? s[j] * inv : 0.f;
}

// ===========================================================================
// Tensor-core AV: y[i,d] = sum_j att[i,j] * v[j,d].  att split on the fly,
// v pre-split bf16 via ldmatrix.trans. 128x64 per CTA, K-chunks of 32.
// ===========================================================================
constexpr int APAD = 40;
constexpr int VPAD = 72;

__global__ __launch_bounds__(256, 1)
void av_mma(const float* __restrict__ att) {
    const int bh = blockIdx.z;
    const int b  = bh >> 4;
    const int h  = bh & 15;
    const int i0 = blockIdx.y * 128;

    __shared__ __nv_bfloat16 sAh[128][APAD];
    __shared__ __nv_bfloat16 sAl[128][APAD];
    __shared__ __nv_bfloat16 sVh[32][VPAD];
    __shared__ __nv_bfloat16 sVl[32][VPAD];

    const int tid  = threadIdx.x;
    const int wid  = tid >> 5;
    const int lane = tid & 31;
    const int warp_m = wid & 3;      // 4 x 32 rows
    const int warp_n = wid >> 2;     // 2 x 32 cols

    const float* arow = att + (size_t)bh * T * T;
    const size_t vbase = ((size_t)b * T) * DIM + h * HD;

    float c[2][4][4] = {};

    const int nch = (i0 + 128) / 32;
    for (int ch = 0; ch < nch; ++ch) {
        const int k0 = ch * 32;
        // att chunk 128x32 fp32 -> split
#pragma unroll
        for (int i = 0; i < 4; ++i) {
            const int idx = tid + i * 256;
            const int row = idx >> 3, c4 = (idx & 7) * 4;
            float4 a = *(const float4*)(arow + (size_t)(i0 + row) * T + k0 + c4);
            uint2 hi, lo;
            split4(a, hi, lo);
            *(uint2*)&sAh[row][c4] = hi;
            *(uint2*)&sAl[row][c4] = lo;
        }
        // v chunk 32x64 bf16 hi/lo
        {
            const int row = tid >> 3;          // 0..31
            const int c8  = (tid & 7) * 8;     // 0..56
            const size_t off = vbase + (size_t)(k0 + row) * DIM + c8;
            *(uint4*)&sVh[row][c8] = *(const uint4*)(g_vhi + off);
            *(uint4*)&sVl[row][c8] = *(const uint4*)(g_vlo + off);
        }
        __syncthreads();

#pragma unroll
        for (int ks = 0; ks < 2; ++ks) {
            const int kc = ks * 16;
            uint32_t ah[2][4], al[2][4], bh[4][2], bl[4][2];
#pragma unroll
            for (int mt = 0; mt < 2; ++mt) {
                const int r   = warp_m * 32 + mt * 16 + (lane & 15);
                const int col = kc + ((lane >> 4) << 3);
                ldsm_x4(ah[mt][0], ah[mt][1], ah[mt][2], ah[mt][3],
                        smem_u32(&sAh[r][col]));
                ldsm_x4(al[mt][0], al[mt][1], al[mt][2], al[mt][3],
                        smem_u32(&sAl[r][col]));
            }
#pragma unroll
            for (int nt = 0; nt < 4; ++nt) {
                const int kr = kc + (lane & 15);
                const int nc = warp_n * 32 + nt * 8;
                ldsm_x2_t(bh[nt][0], bh[nt][1], smem_u32(&sVh[kr][nc]));
                ldsm_x2_t(bl[nt][0], bl[nt][1], smem_u32(&sVl[kr][nc]));
            }
#pragma unroll
            for (int mt = 0; mt < 2; ++mt)
#pragma unroll
                for (int nt = 0; nt < 4; ++nt) {
                    mma_bf16(c[mt][nt], ah[mt], bh[nt]);
                    mma_bf16(c[mt][nt], ah[mt], bl[nt]);
                    mma_bf16(c[mt][nt], al[mt], bh[nt]);
                }
        }
        __syncthreads();
    }

#pragma unroll
    for (int mt = 0; mt < 2; ++mt) {
        const int r0 = i0 + warp_m * 32 + mt * 16 + (lane >> 2);
#pragma unroll
        for (int nt = 0; nt < 4; ++nt) {
            const int cc = warp_n * 32 + nt * 8 + (lane & 3) * 2;
            float* y0 = g_y + ((size_t)b * T + r0) * DIM + h * HD + cc;
            *(float2*)y0              = make_float2(c[mt][nt][0], c[mt][nt][1]);
            *(float2*)(y0 + 8 * DIM)  = make_float2(c[mt][nt][2], c[mt][nt][3]);
        }
    }
}

// ===========================================================================
extern "C" void kernel_launch(void* const* d_in, const int* in_sizes, int n_in,
                              void* d_out, int out_size) {
    const float* Q  = (const float*)d_in[0];
    const float* K  = (const float*)d_in[1];
    const float* V  = (const float*)d_in[2];
    const float* Wq = (const float*)d_in[3];
    const float* Wk = (const float*)d_in[4];
    const float* Wv = (const float*)d_in[5];
    const float* Wo = (const float*)d_in[6];
    float* out = (float*)d_out;

    __nv_bfloat16 *qhi, *qlo, *khi, *klo, *vhi, *vlo;
    float *gy, *graw;
    cudaGetSymbolAddress((void**)&qhi, g_qhi);
    cudaGetSymbolAddress((void**)&qlo, g_qlo);
    cudaGetSymbolAddress((void**)&khi, g_khi);
    cudaGetSymbolAddress((void**)&klo, g_klo);
    cudaGetSymbolAddress((void**)&vhi, g_vhi);
    cudaGetSymbolAddress((void**)&vlo, g_vlo);
    cudaGetSymbolAddress((void**)&gy,   g_y);
    cudaGetSymbolAddress((void**)&graw, g_raw);

    float* att = ((size_t)out_size >= Y_SIZE + ATT_SIZE) ? (out + Y_SIZE) : graw;

    cudaFuncSetAttribute(scores_mma, cudaFuncAttributeMaxDynamicSharedMemorySize,
                         SCORES_SMEM);

    dim3 thr(256);
    dim3 gGemm(NDIM / 128, BT / 128);   // (8, 32)

    // 1) Projections -> pre-split bf16 hi/lo
    gemm_bf16x3<true><<<gGemm, thr>>>(Q, Wq, nullptr, qhi, qlo);
    gemm_bf16x3<true><<<gGemm, thr>>>(K, Wk, nullptr, khi, klo);
    gemm_bf16x3<true><<<gGemm, thr>>>(V, Wv, nullptr, vhi, vlo);

    // 2) Raw causal scores (tensor cores)
    dim3 gScore(T / 128, T / 128, B * H);
    scores_mma<<<gScore, thr, SCORES_SMEM>>>(graw);

    // 3) Row softmax -> att
    softmax_kernel<<<(unsigned)(B * H * T), thr>>>(graw, att);

    // 4) y = att @ v (tensor cores)
    dim3 gAV(1, T / 128, B * H);
    av_mma<<<gAV, thr>>>(att);

    // 5) out = y @ Wo^T
    gemm_bf16x3<false><<<gGemm, thr>>>(gy, Wo, out, nullptr, nullptr);
}

// round 11
// speedup vs baseline: 2.4512x; 1.1937x over previous
#include <cuda_runtime.h>
#include <cuda_bf16.h>
#include <cstdint>
#include <cstddef>

// Problem constants
constexpr int B   = 2;
constexpr int T   = 2048;
constexpr int DIM = 1024;
constexpr int H   = 16;
constexpr int HD  = 64;
constexpr int BT  = B * T;        // 4096
constexpr float SCALE = 0.03125f; // 1/sqrt(1024)

constexpr size_t Y_SIZE   = (size_t)BT * DIM;
constexpr size_t ATT_SIZE = (size_t)B * H * T * T;

// Scratch (allocation-free rule: __device__ globals)
__device__ __nv_bfloat16 g_qhi[BT * DIM];
__device__ __nv_bfloat16 g_qlo[BT * DIM];
__device__ __nv_bfloat16 g_khi[BT * DIM];
__device__ __nv_bfloat16 g_klo[BT * DIM];
__device__ __nv_bfloat16 g_vhi[BT * DIM];
__device__ __nv_bfloat16 g_vlo[BT * DIM];
__device__ float g_y[BT * DIM];
__device__ float g_att_fb[ATT_SIZE];   // fallback att if out buffer lacks room

// ===========================================================================
// mma.sync helpers (standard PTX ISA — legal on plain sm_103 target)
// ===========================================================================
__device__ __forceinline__ uint32_t smem_u32(const void* p) {
    uint32_t a;
    asm("{ .reg .u64 t; cvta.to.shared.u64 t, %1; cvt.u32.u64 %0, t; }" : "=r"(a) : "l"(p));
    return a;
}
__device__ __forceinline__ void ldsm_x4(uint32_t& r0, uint32_t& r1, uint32_t& r2,
                                        uint32_t& r3, uint32_t addr) {
    asm volatile("ldmatrix.sync.aligned.m8n8.x4.shared.b16 {%0,%1,%2,%3}, [%4];"
                 : "=r"(r0), "=r"(r1), "=r"(r2), "=r"(r3) : "r"(addr));
}
__device__ __forceinline__ void ldsm_x2(uint32_t& r0, uint32_t& r1, uint32_t addr) {
    asm volatile("ldmatrix.sync.aligned.m8n8.x2.shared.b16 {%0,%1}, [%2];"
                 : "=r"(r0), "=r"(r1) : "r"(addr));
}
__device__ __forceinline__ void ldsm_x2_t(uint32_t& r0, uint32_t& r1, uint32_t addr) {
    asm volatile("ldmatrix.sync.aligned.m8n8.x2.trans.shared.b16 {%0,%1}, [%2];"
                 : "=r"(r0), "=r"(r1) : "r"(addr));
}
__device__ __forceinline__ void mma_bf16(float* c, const uint32_t* a, const uint32_t* b) {
    asm volatile(
        "mma.sync.aligned.m16n8k16.row.col.f32.bf16.bf16.f32 "
        "{%0,%1,%2,%3}, {%4,%5,%6,%7}, {%8,%9}, {%0,%1,%2,%3};"
        : "+f"(c[0]), "+f"(c[1]), "+f"(c[2]), "+f"(c[3])
        : "r"(a[0]), "r"(a[1]), "r"(a[2]), "r"(a[3]), "r"(b[0]), "r"(b[1]));
}
__device__ __forceinline__ void split4(float4 v, uint2& hi, uint2& lo) {
    __nv_bfloat16 h0 = __float2bfloat16_rn(v.x);
    __nv_bfloat16 h1 = __float2bfloat16_rn(v.y);
    __nv_bfloat16 h2 = __float2bfloat16_rn(v.z);
    __nv_bfloat16 h3 = __float2bfloat16_rn(v.w);
    __nv_bfloat16 l0 = __float2bfloat16_rn(v.x - __bfloat162float(h0));
    __nv_bfloat16 l1 = __float2bfloat16_rn(v.y - __bfloat162float(h1));
    __nv_bfloat16 l2 = __float2bfloat16_rn(v.z - __bfloat162float(h2));
    __nv_bfloat16 l3 = __float2bfloat16_rn(v.w - __bfloat162float(h3));
    __nv_bfloat162 hA = {h0, h1}, hB = {h2, h3}, lA = {l0, l1}, lB = {l2, l3};
    hi = make_uint2(*(uint32_t*)&hA, *(uint32_t*)&hB);
    lo = make_uint2(*(uint32_t*)&lA, *(uint32_t*)&lB);
}
__device__ __forceinline__ void pack2(float x, float y, uint32_t& hi, uint32_t& lo) {
    __nv_bfloat16 hx = __float2bfloat16_rn(x);
    __nv_bfloat16 hy = __float2bfloat16_rn(y);
    __nv_bfloat162 hp = {hx, hy};
    __nv_bfloat162 lp = {__float2bfloat16_rn(x - __bfloat162float(hx)),
                         __float2bfloat16_rn(y - __bfloat162float(hy))};
    hi = *(uint32_t*)&hp;
    lo = *(uint32_t*)&lp;
}

// ===========================================================================
// bf16x3 split GEMM: C[4096,1024] = A[4096,1024] @ W[1024,1024]^T
// SPLIT=true: write C as bf16 hi/lo pair buffers. SPLIT=false: fp32 C.
// ===========================================================================
constexpr int KDIM = 1024;
constexpr int NDIM = 1024;
constexpr int KCH  = 32;
constexpr int NCHG = KDIM / KCH;
constexpr int SPAD = 40;

template <bool SPLIT>
__global__ __launch_bounds__(256, 1)
void gemm_bf16x3(const float* __restrict__ A, const float* __restrict__ W,
                 float* __restrict__ C,
                 __nv_bfloat16* __restrict__ Chi, __nv_bfloat16* __restrict__ Clo) {
    __shared__ __nv_bfloat16 sAhi[128][SPAD];
    __shared__ __nv_bfloat16 sAlo[128][SPAD];
    __shared__ __nv_bfloat16 sWhi[128][SPAD];
    __shared__ __nv_bfloat16 sWlo[128][SPAD];

    const int tid  = threadIdx.x;
    const int wid  = tid >> 5;
    const int lane = tid & 31;
    const int warp_m = wid >> 2;
    const int warp_n = wid & 3;
    const int m0 = blockIdx.y * 128;
    const int n0 = blockIdx.x * 128;

    float c[4][4][4] = {};
    float4 pa[4], pw[4];

#pragma unroll
    for (int i = 0; i < 4; ++i) {
        const int idx = tid + i * 256;
        const int row = idx >> 3, c4 = (idx & 7) * 4;
        pa[i] = *(const float4*)(A + (size_t)(m0 + row) * KDIM + c4);
        pw[i] = *(const float4*)(W + (size_t)(n0 + row) * KDIM + c4);
    }

    for (int ch = 0; ch < NCHG; ++ch) {
#pragma unroll
        for (int i = 0; i < 4; ++i) {
            const int idx = tid + i * 256;
            const int row = idx >> 3, c4 = (idx & 7) * 4;
            uint2 hi, lo;
            split4(pa[i], hi, lo);
            *(uint2*)&sAhi[row][c4] = hi;
            *(uint2*)&sAlo[row][c4] = lo;
            split4(pw[i], hi, lo);
            *(uint2*)&sWhi[row][c4] = hi;
            *(uint2*)&sWlo[row][c4] = lo;
        }
        __syncthreads();

        if (ch + 1 < NCHG) {
            const int k0n = (ch + 1) * KCH;
#pragma unroll
            for (int i = 0; i < 4; ++i) {
                const int idx = tid + i * 256;
                const int row = idx >> 3, c4 = (idx & 7) * 4;
                pa[i] = *(const float4*)(A + (size_t)(m0 + row) * KDIM + k0n + c4);
                pw[i] = *(const float4*)(W + (size_t)(n0 + row) * KDIM + k0n + c4);
            }
        }

#pragma unroll
        for (int ks = 0; ks < 2; ++ks) {
            const int kc = ks * 16;
            uint32_t ah[4][4], al[4][4], bh[4][2], bl[4][2];
#pragma unroll
            for (int mt = 0; mt < 4; ++mt) {
                const int r   = warp_m * 64 + mt * 16 + (lane & 15);
                const int col = kc + ((lane >> 4) << 3);
                ldsm_x4(ah[mt][0], ah[mt][1], ah[mt][2], ah[mt][3],
                        smem_u32(&sAhi[r][col]));
                ldsm_x4(al[mt][0], al[mt][1], al[mt][2], al[mt][3],
                        smem_u32(&sAlo[r][col]));
            }
#pragma unroll
            for (int nt = 0; nt < 4; ++nt) {
                const int t   = lane & 15;
                const int r   = warp_n * 32 + nt * 8 + (t & 7);
                const int col = kc + ((t >> 3) << 3);
                ldsm_x2(bh[nt][0], bh[nt][1], smem_u32(&sWhi[r][col]));
                ldsm_x2(bl[nt][0], bl[nt][1], smem_u32(&sWlo[r][col]));
            }
#pragma unroll
            for (int mt = 0; mt < 4; ++mt)
#pragma unroll
                for (int nt = 0; nt < 4; ++nt) {
                    mma_bf16(c[mt][nt], ah[mt], bh[nt]);
                    mma_bf16(c[mt][nt], ah[mt], bl[nt]);
                    mma_bf16(c[mt][nt], al[mt], bh[nt]);
                }
        }
        __syncthreads();
    }

#pragma unroll
    for (int mt = 0; mt < 4; ++mt) {
        const int r0 = m0 + warp_m * 64 + mt * 16 + (lane >> 2);
#pragma unroll
        for (int nt = 0; nt < 4; ++nt) {
            const int cc = n0 + warp_n * 32 + nt * 8 + (lane & 3) * 2;
            if (SPLIT) {
#pragma unroll
                for (int rr = 0; rr < 2; ++rr) {
                    const size_t off = (size_t)(r0 + rr * 8) * NDIM + cc;
                    uint32_t hp, lp;
                    pack2(c[mt][nt][rr * 2], c[mt][nt][rr * 2 + 1], hp, lp);
                    *(uint32_t*)(Chi + off) = hp;
                    *(uint32_t*)(Clo + off) = lp;
                }
            } else {
                *(float2*)(C + (size_t)r0 * NDIM + cc)       = make_float2(c[mt][nt][0], c[mt][nt][1]);
                *(float2*)(C + (size_t)(r0 + 8) * NDIM + cc) = make_float2(c[mt][nt][2], c[mt][nt][3]);
            }
        }
    }
}

// ===========================================================================
// Fused flash attention: scores + softmax + att write + AV, per 128-row block.
// Two-pass recompute: pass A gets exact row max m and sum l (no stores);
// pass B recomputes scores, writes att = exp(s-m)/l, and accumulates
// y += P@V with P split to bf16 hi/lo straight from registers.
// 8 warps, each owns 16 rows. Q fragments live in registers for the whole CTA.
// ===========================================================================
constexpr int FPAD = 72;                                      // 64 -> 72 pad
constexpr int FUSED_SMEM = 6 * 128 * FPAD * 2;                // 110,592 B

__device__ __forceinline__ void compute_scores(
    const __nv_bfloat16* __restrict__ sKh, const __nv_bfloat16* __restrict__ sKl,
    const uint32_t qh[4][4], const uint32_t ql[4][4],
    int lane, float c[16][4]) {
#pragma unroll
    for (int nt = 0; nt < 16; ++nt) {
        c[nt][0] = 0.f; c[nt][1] = 0.f; c[nt][2] = 0.f; c[nt][3] = 0.f;
    }
    const int t15 = lane & 15;
#pragma unroll
    for (int ks = 0; ks < 4; ++ks) {
        const int col = ks * 16 + ((t15 >> 3) << 3);
#pragma unroll
        for (int ng = 0; ng < 4; ++ng) {       // groups of 4 n-tiles
            uint32_t bhf[4][2], blf[4][2];
#pragma unroll
            for (int q = 0; q < 4; ++q) {
                const int r = (ng * 4 + q) * 8 + (t15 & 7);
                ldsm_x2(bhf[q][0], bhf[q][1], smem_u32(&sKh[r * FPAD + col]));
                ldsm_x2(blf[q][0], blf[q][1], smem_u32(&sKl[r * FPAD + col]));
            }
#pragma unroll
            for (int q = 0; q < 4; ++q) {
                float* cc = c[ng * 4 + q];
                mma_bf16(cc, qh[ks], bhf[q]);
                mma_bf16(cc, qh[ks], blf[q]);
                mma_bf16(cc, ql[ks], bhf[q]);
            }
        }
    }
}

__global__ __launch_bounds__(256, 1)
void fused_attn(float* __restrict__ att) {
    const int bh = blockIdx.y;
    const int b  = bh >> 4;
    const int h  = bh & 15;
    const int i0 = blockIdx.x * 128;

    extern __shared__ __nv_bfloat16 sm[];
    __nv_bfloat16* sQh = sm;
    __nv_bfloat16* sQl = sm + 128 * FPAD;
    __nv_bfloat16* sKh = sm + 2 * 128 * FPAD;
    __nv_bfloat16* sKl = sm + 3 * 128 * FPAD;
    __nv_bfloat16* sVh = sm + 4 * 128 * FPAD;
    __nv_bfloat16* sVl = sm + 5 * 128 * FPAD;

    const int tid  = threadIdx.x;
    const int wid  = tid >> 5;
    const int lane = tid & 31;
    const size_t base = ((size_t)b * T) * DIM + h * HD;
    float* arow = att + (size_t)bh * T * T;

    // ---- Load Q tile (128x64 hi/lo) and build persistent A fragments ----
#pragma unroll
    for (int i = 0; i < 4; ++i) {
        const int idx = tid + i * 256;
        const int row = idx >> 3, c8 = (idx & 7) * 8;
        const size_t off = base + (size_t)(i0 + row) * DIM + c8;
        *(uint4*)&sQh[row * FPAD + c8] = *(const uint4*)(g_qhi + off);
        *(uint4*)&sQl[row * FPAD + c8] = *(const uint4*)(g_qlo + off);
    }
    __syncthreads();
    uint32_t qh[4][4], ql[4][4];
#pragma unroll
    for (int ks = 0; ks < 4; ++ks) {
        const int r   = wid * 16 + (lane & 15);
        const int col = ks * 16 + ((lane >> 4) << 3);
        ldsm_x4(qh[ks][0], qh[ks][1], qh[ks][2], qh[ks][3], smem_u32(&sQh[r * FPAD + col]));
        ldsm_x4(ql[ks][0], ql[ks][1], ql[ks][2], ql[ks][3], smem_u32(&sQl[r * FPAD + col]));
    }

    const int ntiles = i0 / 128 + 1;
    const int row_lo = (wid << 4) + (lane >> 2);    // local row (c0,c1); +8 for c2,c3
    float m0 = -1e30f, m1 = -1e30f, l0 = 0.f, l1 = 0.f;

    // ---- Pass A: exact row max + sum (no stores) ----
    for (int t = 0; t < ntiles; ++t) {
        const int j0 = t * 128;
        __syncthreads();
#pragma unroll
        for (int i = 0; i < 4; ++i) {
            const int idx = tid + i * 256;
            const int row = idx >> 3, c8 = (idx & 7) * 8;
            const size_t off = base + (size_t)(j0 + row) * DIM + c8;
            *(uint4*)&sKh[row * FPAD + c8] = *(const uint4*)(g_khi + off);
            *(uint4*)&sKl[row * FPAD + c8] = *(const uint4*)(g_klo + off);
        }
        __syncthreads();

        float c[16][4];
        compute_scores(sKh, sKl, qh, ql, lane, c);

        const bool diag = (j0 == i0);
        float tm0 = -1e30f, tm1 = -1e30f;
#pragma unroll
        for (int nt = 0; nt < 16; ++nt) {
            float s0 = c[nt][0] * SCALE, s1 = c[nt][1] * SCALE;
            float s2 = c[nt][2] * SCALE, s3 = c[nt][3] * SCALE;
            if (diag) {
                const int c0 = nt * 8 + ((lane & 3) << 1);
                if (c0     > row_lo)     s0 = -1e30f;
                if (c0 + 1 > row_lo)     s1 = -1e30f;
                if (c0     > row_lo + 8) s2 = -1e30f;
                if (c0 + 1 > row_lo + 8) s3 = -1e30f;
            }
            c[nt][0] = s0; c[nt][1] = s1; c[nt][2] = s2; c[nt][3] = s3;
            tm0 = fmaxf(tm0, fmaxf(s0, s1));
            tm1 = fmaxf(tm1, fmaxf(s2, s3));
        }
        tm0 = fmaxf(tm0, __shfl_xor_sync(0xffffffff, tm0, 1));
        tm0 = fmaxf(tm0, __shfl_xor_sync(0xffffffff, tm0, 2));
        tm1 = fmaxf(tm1, __shfl_xor_sync(0xffffffff, tm1, 1));
        tm1 = fmaxf(tm1, __shfl_xor_sync(0xffffffff, tm1, 2));
        const float mn0 = fmaxf(m0, tm0);
        const float mn1 = fmaxf(m1, tm1);
        float sm0 = 0.f, sm1 = 0.f;
#pragma unroll
        for (int nt = 0; nt < 16; ++nt) {
            sm0 += __expf(c[nt][0] - mn0) + __expf(c[nt][1] - mn0);
            sm1 += __expf(c[nt][2] - mn1) + __expf(c[nt][3] - mn1);
        }
        sm0 += __shfl_xor_sync(0xffffffff, sm0, 1);
        sm0 += __shfl_xor_sync(0xffffffff, sm0, 2);
        sm1 += __shfl_xor_sync(0xffffffff, sm1, 1);
        sm1 += __shfl_xor_sync(0xffffffff, sm1, 2);
        l0 = l0 * __expf(m0 - mn0) + sm0;  m0 = mn0;
        l1 = l1 * __expf(m1 - mn1) + sm1;  m1 = mn1;
    }
    const float inv0 = 1.f / l0;
    const float inv1 = 1.f / l1;

    // ---- Pass B: recompute, write att, accumulate y = P@V ----
    float y[8][4] = {};
    for (int t = 0; t < ntiles; ++t) {
        const int j0 = t * 128;
        __syncthreads();
#pragma unroll
        for (int i = 0; i < 4; ++i) {
            const int idx = tid + i * 256;
            const int row = idx >> 3, c8 = (idx & 7) * 8;
            const size_t off = base + (size_t)(j0 + row) * DIM + c8;
            *(uint4*)&sKh[row * FPAD + c8] = *(const uint4*)(g_khi + off);
            *(uint4*)&sKl[row * FPAD + c8] = *(const uint4*)(g_klo + off);
            *(uint4*)&sVh[row * FPAD + c8] = *(const uint4*)(g_vhi + off);
            *(uint4*)&sVl[row * FPAD + c8] = *(const uint4*)(g_vlo + off);
        }
        __syncthreads();

        float c[16][4];
        compute_scores(sKh, sKl, qh, ql, lane, c);

        const bool diag = (j0 == i0);
#pragma unroll
        for (int nt = 0; nt < 16; ++nt) {
            float p0 = __expf(c[nt][0] * SCALE - m0) * inv0;
            float p1 = __expf(c[nt][1] * SCALE - m0) * inv0;
            float p2 = __expf(c[nt][2] * SCALE - m1) * inv1;
            float p3 = __expf(c[nt][3] * SCALE - m1) * inv1;
            if (diag) {
                const int c0 = nt * 8 + ((lane & 3) << 1);
                if (c0     > row_lo)     p0 = 0.f;
                if (c0 + 1 > row_lo)     p1 = 0.f;
                if (c0     > row_lo + 8) p2 = 0.f;
                if (c0 + 1 > row_lo + 8) p3 = 0.f;
            }
            c[nt][0] = p0; c[nt][1] = p1; c[nt][2] = p2; c[nt][3] = p3;
            // write att
            const int cc = j0 + nt * 8 + ((lane & 3) << 1);
            *(float2*)(arow + (size_t)(i0 + row_lo) * T + cc)     = make_float2(p0, p1);
            *(float2*)(arow + (size_t)(i0 + row_lo + 8) * T + cc) = make_float2(p2, p3);
        }

        // y += P @ V  (P from registers, split hi/lo; V via ldmatrix.trans)
#pragma unroll
        for (int kg = 0; kg < 8; ++kg) {
            const int f0 = 2 * kg, f1 = 2 * kg + 1;
            uint32_t ah[4], al[4];
            pack2(c[f0][0], c[f0][1], ah[0], al[0]);
            pack2(c[f0][2], c[f0][3], ah[1], al[1]);
            pack2(c[f1][0], c[f1][1], ah[2], al[2]);
            pack2(c[f1][2], c[f1][3], ah[3], al[3]);
            const int kr = kg * 16 + (lane & 15);
#pragma unroll
            for (int nt2 = 0; nt2 < 8; ++nt2) {
                uint32_t vh[2], vl[2];
                ldsm_x2_t(vh[0], vh[1], smem_u32(&sVh[kr * FPAD + nt2 * 8]));
                ldsm_x2_t(vl[0], vl[1], smem_u32(&sVl[kr * FPAD + nt2 * 8]));
                mma_bf16(y[nt2], ah, vh);
                mma_bf16(y[nt2], ah, vl);
                mma_bf16(y[nt2], al, vh);
            }
        }
    }

    // ---- Write y ----
#pragma unroll
    for (int nt2 = 0; nt2 < 8; ++nt2) {
        const int r0 = i0 + row_lo;
        float* y0 = g_y + ((size_t)b * T + r0) * DIM + h * HD + nt2 * 8 + ((lane & 3) << 1);
        *(float2*)y0             = make_float2(y[nt2][0], y[nt2][1]);
        *(float2*)(y0 + 8 * DIM) = make_float2(y[nt2][2], y[nt2][3]);
    }

    // ---- Zero-fill att cols [i0+128, T) for this row block ----
    const int start = i0 + 128;
    if (start < T) {
        const int spanv = (T - start) >> 2;          // float4s per row
        // stream rows: each warp takes rows wid, wid+8, ...; lanes cover cols
        for (int r = wid; r < 128; r += 8) {
            float* dst = arow + (size_t)(i0 + r) * T + start;
            for (int cq = lane; cq < spanv; cq += 32)
                *(float4*)(dst + cq * 4) = make_float4(0.f, 0.f, 0.f, 0.f);
        }
    }
}

// ===========================================================================
extern "C" void kernel_launch(void* const* d_in, const int* in_sizes, int n_in,
                              void* d_out, int out_size) {
    const float* Q  = (const float*)d_in[0];
    const float* K  = (const float*)d_in[1];
    const float* V  = (const float*)d_in[2];
    const float* Wq = (const float*)d_in[3];
    const float* Wk = (const float*)d_in[4];
    const float* Wv = (const float*)d_in[5];
    const float* Wo = (const float*)d_in[6];
    float* out = (float*)d_out;

    __nv_bfloat16 *qhi, *qlo, *khi, *klo, *vhi, *vlo;
    float *gy, *gfb;
    cudaGetSymbolAddress((void**)&qhi, g_qhi);
    cudaGetSymbolAddress((void**)&qlo, g_qlo);
    cudaGetSymbolAddress((void**)&khi, g_khi);
    cudaGetSymbolAddress((void**)&klo, g_klo);
    cudaGetSymbolAddress((void**)&vhi, g_vhi);
    cudaGetSymbolAddress((void**)&vlo, g_vlo);
    cudaGetSymbolAddress((void**)&gy,  g_y);
    cudaGetSymbolAddress((void**)&gfb, g_att_fb);

    float* att = ((size_t)out_size >= Y_SIZE + ATT_SIZE) ? (out + Y_SIZE) : gfb;

    cudaFuncSetAttribute(fused_attn, cudaFuncAttributeMaxDynamicSharedMemorySize,
                         FUSED_SMEM);

    dim3 thr(256);
    dim3 gGemm(NDIM / 128, BT / 128);   // (8, 32)

    // 1) Projections -> pre-split bf16 hi/lo
    gemm_bf16x3<true><<<gGemm, thr>>>(Q, Wq, nullptr, qhi, qlo);
    gemm_bf16x3<true><<<gGemm, thr>>>(K, Wk, nullptr, khi, klo);
    gemm_bf16x3<true><<<gGemm, thr>>>(V, Wv, nullptr, vhi, vlo);

    // 2) Fused scores + softmax + att + AV
    dim3 gFuse(T / 128, B * H);         // (16, 32)
    fused_attn<<<gFuse, thr, FUSED_SMEM>>>(att);

    // 3) out = y @ Wo^T
    gemm_bf16x3<false><<<gGemm, thr>>>(gy, Wo, out, nullptr, nullptr);
}

// round 13
// speedup vs baseline: 2.5251x; 1.0302x over previous
#include <cuda_runtime.h>
#include <cuda_bf16.h>
#include <cstdint>
#include <cstddef>

// Problem constants
constexpr int B   = 2;
constexpr int T   = 2048;
constexpr int DIM = 1024;
constexpr int H   = 16;
constexpr int HD  = 64;
constexpr int BT  = B * T;        // 4096
constexpr float SCALE = 0.03125f; // 1/sqrt(1024)
constexpr float LOG2E = 1.44269504088896341f;
constexpr float QMUL  = SCALE * LOG2E;   // fold into q projection

constexpr size_t Y_SIZE   = (size_t)BT * DIM;
constexpr size_t ATT_SIZE = (size_t)B * H * T * T;

// Scratch (allocation-free rule: __device__ globals)
__device__ __nv_bfloat16 g_qhi[BT * DIM];
__device__ __nv_bfloat16 g_qlo[BT * DIM];
__device__ __nv_bfloat16 g_khi[BT * DIM];
__device__ __nv_bfloat16 g_klo[BT * DIM];
__device__ __nv_bfloat16 g_vhi[BT * DIM];
__device__ __nv_bfloat16 g_vlo[BT * DIM];
__device__ float g_y[BT * DIM];
__device__ float g_att_fb[ATT_SIZE];   // fallback att if out buffer lacks room

// ===========================================================================
// PTX helpers (standard ISA — legal on plain sm_103 target)
// ===========================================================================
__device__ __forceinline__ uint32_t smem_u32(const void* p) {
    uint32_t a;
    asm("{ .reg .u64 t; cvta.to.shared.u64 t, %1; cvt.u32.u64 %0, t; }" : "=r"(a) : "l"(p));
    return a;
}
__device__ __forceinline__ void ldsm_x4(uint32_t& r0, uint32_t& r1, uint32_t& r2,
                                        uint32_t& r3, uint32_t addr) {
    asm volatile("ldmatrix.sync.aligned.m8n8.x4.shared.b16 {%0,%1,%2,%3}, [%4];"
                 : "=r"(r0), "=r"(r1), "=r"(r2), "=r"(r3) : "r"(addr));
}
__device__ __forceinline__ void ldsm_x2(uint32_t& r0, uint32_t& r1, uint32_t addr) {
    asm volatile("ldmatrix.sync.aligned.m8n8.x2.shared.b16 {%0,%1}, [%2];"
                 : "=r"(r0), "=r"(r1) : "r"(addr));
}
__device__ __forceinline__ void ldsm_x2_t(uint32_t& r0, uint32_t& r1, uint32_t addr) {
    asm volatile("ldmatrix.sync.aligned.m8n8.x2.trans.shared.b16 {%0,%1}, [%2];"
                 : "=r"(r0), "=r"(r1) : "r"(addr));
}
__device__ __forceinline__ void mma_bf16(float* c, const uint32_t* a, const uint32_t* b) {
    asm volatile(
        "mma.sync.aligned.m16n8k16.row.col.f32.bf16.bf16.f32 "
        "{%0,%1,%2,%3}, {%4,%5,%6,%7}, {%8,%9}, {%0,%1,%2,%3};"
        : "+f"(c[0]), "+f"(c[1]), "+f"(c[2]), "+f"(c[3])
        : "r"(a[0]), "r"(a[1]), "r"(a[2]), "r"(a[3]), "r"(b[0]), "r"(b[1]));
}
__device__ __forceinline__ void cp16(uint32_t dst, const void* src) {
    asm volatile("cp.async.ca.shared.global [%0], [%1], 16;" :: "r"(dst), "l"(src));
}
__device__ __forceinline__ void cp_commit() {
    asm volatile("cp.async.commit_group;" ::: "memory");
}
template <int N>
__device__ __forceinline__ void cp_wait() {
    asm volatile("cp.async.wait_group %0;" :: "n"(N) : "memory");
}
__device__ __forceinline__ void split4(float4 v, uint2& hi, uint2& lo) {
    __nv_bfloat16 h0 = __float2bfloat16_rn(v.x);
    __nv_bfloat16 h1 = __float2bfloat16_rn(v.y);
    __nv_bfloat16 h2 = __float2bfloat16_rn(v.z);
    __nv_bfloat16 h3 = __float2bfloat16_rn(v.w);
    __nv_bfloat16 l0 = __float2bfloat16_rn(v.x - __bfloat162float(h0));
    __nv_bfloat16 l1 = __float2bfloat16_rn(v.y - __bfloat162float(h1));
    __nv_bfloat16 l2 = __float2bfloat16_rn(v.z - __bfloat162float(h2));
    __nv_bfloat16 l3 = __float2bfloat16_rn(v.w - __bfloat162float(h3));
    __nv_bfloat162 hA = {h0, h1}, hB = {h2, h3}, lA = {l0, l1}, lB = {l2, l3};
    hi = make_uint2(*(uint32_t*)&hA, *(uint32_t*)&hB);
    lo = make_uint2(*(uint32_t*)&lA, *(uint32_t*)&lB);
}
__device__ __forceinline__ void pack2(float x, float y, uint32_t& hi, uint32_t& lo) {
    __nv_bfloat16 hx = __float2bfloat16_rn(x);
    __nv_bfloat16 hy = __float2bfloat16_rn(y);
    __nv_bfloat162 hp = {hx, hy};
    __nv_bfloat162 lp = {__float2bfloat16_rn(x - __bfloat162float(hx)),
                         __float2bfloat16_rn(y - __bfloat162float(hy))};
    hi = *(uint32_t*)&hp;
    lo = *(uint32_t*)&lp;
}

// ===========================================================================
// Shared GEMM core: 128x128 tile, bf16x3 split, K-chunk 32.
// Epilogue is a functor struct (no --extended-lambda on harness nvcc).
// ===========================================================================
constexpr int KDIM = 1024;
constexpr int NDIM = 1024;
constexpr int KCH  = 32;
constexpr int NCHG = KDIM / KCH;
constexpr int SPAD = 40;

struct EpiSplit {           // write bf16 hi/lo with scale
    __nv_bfloat16* Chi;
    __nv_bfloat16* Clo;
    float mul;
    __device__ __forceinline__ void operator()(int r0, int cc, const float* cf) const {
#pragma unroll
        for (int rr = 0; rr < 2; ++rr) {
            const size_t off = (size_t)(r0 + rr * 8) * NDIM + cc;
            uint32_t hp, lp;
            pack2(cf[rr * 2] * mul, cf[rr * 2 + 1] * mul, hp, lp);
            *(uint32_t*)(Chi + off) = hp;
            *(uint32_t*)(Clo + off) = lp;
        }
    }
};
struct EpiF32 {             // write fp32
    float* C;
    __device__ __forceinline__ void operator()(int r0, int cc, const float* cf) const {
        *(float2*)(C + (size_t)r0 * NDIM + cc)       = make_float2(cf[0], cf[1]);
        *(float2*)(C + (size_t)(r0 + 8) * NDIM + cc) = make_float2(cf[2], cf[3]);
    }
};

template <typename EPI>
__device__ __forceinline__ void gemm_core(const float* __restrict__ A,
                                          const float* __restrict__ W,
                                          int m0, int n0, EPI epi) {
    __shared__ __nv_bfloat16 sAhi[128][SPAD];
    __shared__ __nv_bfloat16 sAlo[128][SPAD];
    __shared__ __nv_bfloat16 sWhi[128][SPAD];
    __shared__ __nv_bfloat16 sWlo[128][SPAD];

    const int tid  = threadIdx.x;
    const int wid  = tid >> 5;
    const int lane = tid & 31;
    const int warp_m = wid >> 2;
    const int warp_n = wid & 3;

    float c[4][4][4] = {};
    float4 pa[4], pw[4];

#pragma unroll
    for (int i = 0; i < 4; ++i) {
        const int idx = tid + i * 256;
        const int row = idx >> 3, c4 = (idx & 7) * 4;
        pa[i] = *(const float4*)(A + (size_t)(m0 + row) * KDIM + c4);
        pw[i] = *(const float4*)(W + (size_t)(n0 + row) * KDIM + c4);
    }

    for (int ch = 0; ch < NCHG; ++ch) {
#pragma unroll
        for (int i = 0; i < 4; ++i) {
            const int idx = tid + i * 256;
            const int row = idx >> 3, c4 = (idx & 7) * 4;
            uint2 hi, lo;
            split4(pa[i], hi, lo);
            *(uint2*)&sAhi[row][c4] = hi;
            *(uint2*)&sAlo[row][c4] = lo;
            split4(pw[i], hi, lo);
            *(uint2*)&sWhi[row][c4] = hi;
            *(uint2*)&sWlo[row][c4] = lo;
        }
        __syncthreads();

        if (ch + 1 < NCHG) {
            const int k0n = (ch + 1) * KCH;
#pragma unroll
            for (int i = 0; i < 4; ++i) {
                const int idx = tid + i * 256;
                const int row = idx >> 3, c4 = (idx & 7) * 4;
                pa[i] = *(const float4*)(A + (size_t)(m0 + row) * KDIM + k0n + c4);
                pw[i] = *(const float4*)(W + (size_t)(n0 + row) * KDIM + k0n + c4);
            }
        }

#pragma unroll
        for (int ks = 0; ks < 2; ++ks) {
            const int kc = ks * 16;
            uint32_t ah[4][4], al[4][4], bh[4][2], bl[4][2];
#pragma unroll
            for (int mt = 0; mt < 4; ++mt) {
                const int r   = warp_m * 64 + mt * 16 + (lane & 15);
                const int col = kc + ((lane >> 4) << 3);
                ldsm_x4(ah[mt][0], ah[mt][1], ah[mt][2], ah[mt][3],
                        smem_u32(&sAhi[r][col]));
                ldsm_x4(al[mt][0], al[mt][1], al[mt][2], al[mt][3],
                        smem_u32(&sAlo[r][col]));
            }
#pragma unroll
            for (int nt = 0; nt < 4; ++nt) {
                const int t   = lane & 15;
                const int r   = warp_n * 32 + nt * 8 + (t & 7);
                const int col = kc + ((t >> 3) << 3);
                ldsm_x2(bh[nt][0], bh[nt][1], smem_u32(&sWhi[r][col]));
                ldsm_x2(bl[nt][0], bl[nt][1], smem_u32(&sWlo[r][col]));
            }
#pragma unroll
            for (int mt = 0; mt < 4; ++mt)
#pragma unroll
                for (int nt = 0; nt < 4; ++nt) {
                    mma_bf16(c[mt][nt], ah[mt], bh[nt]);
                    mma_bf16(c[mt][nt], ah[mt], bl[nt]);
                    mma_bf16(c[mt][nt], al[mt], bh[nt]);
                }
        }
        __syncthreads();
    }

#pragma unroll
    for (int mt = 0; mt < 4; ++mt) {
        const int r0 = m0 + warp_m * 64 + mt * 16 + (lane >> 2);
#pragma unroll
        for (int nt = 0; nt < 4; ++nt) {
            const int cc = n0 + warp_n * 32 + nt * 8 + (lane & 3) * 2;
            epi(r0, cc, c[mt][nt]);
        }
    }
}

// Merged Q/K/V projection (z selects), writing pre-split bf16; Q pre-scaled.
__global__ __launch_bounds__(256, 1)
void gemm_qkv(const float* __restrict__ Q, const float* __restrict__ K,
              const float* __restrict__ V, const float* __restrict__ Wq,
              const float* __restrict__ Wk, const float* __restrict__ Wv) {
    const int z = blockIdx.z;
    const float* A = (z == 0) ? Q : (z == 1) ? K : V;
    const float* W = (z == 0) ? Wq : (z == 1) ? Wk : Wv;
    EpiSplit epi;
    epi.Chi = (z == 0) ? g_qhi : (z == 1) ? g_khi : g_vhi;
    epi.Clo = (z == 0) ? g_qlo : (z == 1) ? g_klo : g_vlo;
    epi.mul = (z == 0) ? QMUL : 1.0f;
    gemm_core(A, W, blockIdx.y * 128, blockIdx.x * 128, epi);
}

// Output projection: fp32 C.
__global__ __launch_bounds__(256, 1)
void gemm_out(const float* __restrict__ A, const float* __restrict__ W,
              float* __restrict__ C) {
    EpiF32 epi;
    epi.C = C;
    gemm_core(A, W, blockIdx.y * 128, blockIdx.x * 128, epi);
}

// ===========================================================================
// Fused flash attention with cp.async double-buffered K/V tiles.
// Scores are in log2 units (q pre-scaled by SCALE*log2e) -> exp2f.
// ===========================================================================
constexpr int FPAD  = 72;
constexpr int TILEB = 128 * FPAD;                 // bf16 elems per buffer
constexpr int FUSED_SMEM = 10 * TILEB * 2;        // Q(2) + K(4) + V(4) = 184,320 B

// async-copy one 128x64 hi/lo tile pair into smem buffers
__device__ __forceinline__ void cp_tile(uint32_t dh, uint32_t dl,
                                        const __nv_bfloat16* __restrict__ gh,
                                        const __nv_bfloat16* __restrict__ gl,
                                        size_t gbase, int tid) {
#pragma unroll
    for (int i = 0; i < 4; ++i) {
        const int idx = tid + i * 256;
        const int row = idx >> 3, c8 = (idx & 7) * 8;
        const size_t off = gbase + (size_t)row * DIM + c8;
        const uint32_t d = (uint32_t)((row * FPAD + c8) * 2);
        cp16(dh + d, gh + off);
        cp16(dl + d, gl + off);
    }
}

__device__ __forceinline__ void compute_scores(
    const __nv_bfloat16* __restrict__ sKh, const __nv_bfloat16* __restrict__ sKl,
    const uint32_t qh[4][4], const uint32_t ql[4][4],
    int lane, float c[16][4]) {
#pragma unroll
    for (int nt = 0; nt < 16; ++nt) {
        c[nt][0] = 0.f; c[nt][1] = 0.f; c[nt][2] = 0.f; c[nt][3] = 0.f;
    }
    const int t15 = lane & 15;
#pragma unroll
    for (int ks = 0; ks < 4; ++ks) {
        const int col = ks * 16 + ((t15 >> 3) << 3);
#pragma unroll
        for (int ng = 0; ng < 4; ++ng) {
            uint32_t bhf[4][2], blf[4][2];
#pragma unroll
            for (int q = 0; q < 4; ++q) {
                const int r = (ng * 4 + q) * 8 + (t15 & 7);
                ldsm_x2(bhf[q][0], bhf[q][1], smem_u32(&sKh[r * FPAD + col]));
                ldsm_x2(blf[q][0], blf[q][1], smem_u32(&sKl[r * FPAD + col]));
            }
#pragma unroll
            for (int q = 0; q < 4; ++q) {
                float* cc = c[ng * 4 + q];
                mma_bf16(cc, qh[ks], bhf[q]);
                mma_bf16(cc, qh[ks], blf[q]);
                mma_bf16(cc, ql[ks], bhf[q]);
            }
        }
    }
}

__global__ __launch_bounds__(256, 1)
void fused_attn(float* __restrict__ att) {
    const int bh = blockIdx.y;
    const int b  = bh >> 4;
    const int h  = bh & 15;
    const int i0 = blockIdx.x * 128;

    extern __shared__ __nv_bfloat16 sm[];
    __nv_bfloat16* sQh = sm;
    __nv_bfloat16* sQl = sm + TILEB;
    __nv_bfloat16* sKh[2] = { sm + 2 * TILEB, sm + 4 * TILEB };
    __nv_bfloat16* sKl[2] = { sm + 3 * TILEB, sm + 5 * TILEB };
    __nv_bfloat16* sVh[2] = { sm + 6 * TILEB, sm + 8 * TILEB };
    __nv_bfloat16* sVl[2] = { sm + 7 * TILEB, sm + 9 * TILEB };
    uint32_t aKh[2] = { smem_u32(sKh[0]), smem_u32(sKh[1]) };
    uint32_t aKl[2] = { smem_u32(sKl[0]), smem_u32(sKl[1]) };
    uint32_t aVh[2] = { smem_u32(sVh[0]), smem_u32(sVh[1]) };
    uint32_t aVl[2] = { smem_u32(sVl[0]), smem_u32(sVl[1]) };

    const int tid  = threadIdx.x;
    const int wid  = tid >> 5;
    const int lane = tid & 31;
    const size_t base = ((size_t)b * T) * DIM + h * HD;
    float* arow = att + (size_t)bh * T * T;
    const int ntiles = i0 / 128 + 1;

    // ---- Load Q tile (regular) + prefetch K tile 0 (async) ----
#pragma unroll
    for (int i = 0; i < 4; ++i) {
        const int idx = tid + i * 256;
        const int row = idx >> 3, c8 = (idx & 7) * 8;
        const size_t off = base + (size_t)(i0 + row) * DIM + c8;
        *(uint4*)&sQh[row * FPAD + c8] = *(const uint4*)(g_qhi + off);
        *(uint4*)&sQl[row * FPAD + c8] = *(const uint4*)(g_qlo + off);
    }
    cp_tile(aKh[0], aKl[0], g_khi, g_klo, base, tid);
    cp_commit();
    __syncthreads();

    uint32_t qh[4][4], ql[4][4];
#pragma unroll
    for (int ks = 0; ks < 4; ++ks) {
        const int r   = wid * 16 + (lane & 15);
        const int col = ks * 16 + ((lane >> 4) << 3);
        ldsm_x4(qh[ks][0], qh[ks][1], qh[ks][2], qh[ks][3], smem_u32(&sQh[r * FPAD + col]));
        ldsm_x4(ql[ks][0], ql[ks][1], ql[ks][2], ql[ks][3], smem_u32(&sQl[r * FPAD + col]));
    }

    const int row_lo = (wid << 4) + (lane >> 2);
    float m0 = -1e30f, m1 = -1e30f, l0 = 0.f, l1 = 0.f;

    // ---- Pass A: exact row max + sum (log2 domain) ----
    for (int t = 0; t < ntiles; ++t) {
        const int bf = t & 1;
        if (t + 1 < ntiles) {
            cp_tile(aKh[bf ^ 1], aKl[bf ^ 1], g_khi, g_klo,
                    base + (size_t)(t + 1) * 128 * DIM, tid);
            cp_commit();
            cp_wait<1>();
        } else {
            cp_wait<0>();
        }
        __syncthreads();

        float c[16][4];
        compute_scores(sKh[bf], sKl[bf], qh, ql, lane, c);

        const bool diag = (t * 128 == i0);
        float tm0 = -1e30f, tm1 = -1e30f;
#pragma unroll
        for (int nt = 0; nt < 16; ++nt) {
            float s0 = c[nt][0], s1 = c[nt][1], s2 = c[nt][2], s3 = c[nt][3];
            if (diag) {
                const int c0 = nt * 8 + ((lane & 3) << 1);
                if (c0     > row_lo)     s0 = -1e30f;
                if (c0 + 1 > row_lo)     s1 = -1e30f;
                if (c0     > row_lo + 8) s2 = -1e30f;
                if (c0 + 1 > row_lo + 8) s3 = -1e30f;
            }
            c[nt][0] = s0; c[nt][1] = s1; c[nt][2] = s2; c[nt][3] = s3;
            tm0 = fmaxf(tm0, fmaxf(s0, s1));
            tm1 = fmaxf(tm1, fmaxf(s2, s3));
        }
        tm0 = fmaxf(tm0, __shfl_xor_sync(0xffffffff, tm0, 1));
        tm0 = fmaxf(tm0, __shfl_xor_sync(0xffffffff, tm0, 2));
        tm1 = fmaxf(tm1, __shfl_xor_sync(0xffffffff, tm1, 1));
        tm1 = fmaxf(tm1, __shfl_xor_sync(0xffffffff, tm1, 2));
        const float mn0 = fmaxf(m0, tm0);
        const float mn1 = fmaxf(m1, tm1);
        float sm0 = 0.f, sm1 = 0.f;
#pragma unroll
        for (int nt = 0; nt < 16; ++nt) {
            sm0 += exp2f(c[nt][0] - mn0) + exp2f(c[nt][1] - mn0);
            sm1 += exp2f(c[nt][2] - mn1) + exp2f(c[nt][3] - mn1);
        }
        sm0 += __shfl_xor_sync(0xffffffff, sm0, 1);
        sm0 += __shfl_xor_sync(0xffffffff, sm0, 2);
        sm1 += __shfl_xor_sync(0xffffffff, sm1, 1);
        sm1 += __shfl_xor_sync(0xffffffff, sm1, 2);
        l0 = l0 * exp2f(m0 - mn0) + sm0;  m0 = mn0;
        l1 = l1 * exp2f(m1 - mn1) + sm1;  m1 = mn1;
        __syncthreads();
    }
    const float inv0 = 1.f / l0;
    const float inv1 = 1.f / l1;

    // ---- Pass B: recompute, write att, accumulate y = P@V ----
    cp_tile(aKh[0], aKl[0], g_khi, g_klo, base, tid);
    cp_tile(aVh[0], aVl[0], g_vhi, g_vlo, base, tid);
    cp_commit();

    float y[8][4] = {};
    for (int t = 0; t < ntiles; ++t) {
        const int bf = t & 1;
        if (t + 1 < ntiles) {
            const size_t gb = base + (size_t)(t + 1) * 128 * DIM;
            cp_tile(aKh[bf ^ 1], aKl[bf ^ 1], g_khi, g_klo, gb, tid);
            cp_tile(aVh[bf ^ 1], aVl[bf ^ 1], g_vhi, g_vlo, gb, tid);
            cp_commit();
            cp_wait<1>();
        } else {
            cp_wait<0>();
        }
        __syncthreads();

        float c[16][4];
        compute_scores(sKh[bf], sKl[bf], qh, ql, lane, c);

        const int j0 = t * 128;
        const bool diag = (j0 == i0);
#pragma unroll
        for (int nt = 0; nt < 16; ++nt) {
            float p0 = exp2f(c[nt][0] - m0) * inv0;
            float p1 = exp2f(c[nt][1] - m0) * inv0;
            float p2 = exp2f(c[nt][2] - m1) * inv1;
            float p3 = exp2f(c[nt][3] - m1) * inv1;
            if (diag) {
                const int c0 = nt * 8 + ((lane & 3) << 1);
                if (c0     > row_lo)     p0 = 0.f;
                if (c0 + 1 > row_lo)     p1 = 0.f;
                if (c0     > row_lo + 8) p2 = 0.f;
                if (c0 + 1 > row_lo + 8) p3 = 0.f;
            }
            c[nt][0] = p0; c[nt][1] = p1; c[nt][2] = p2; c[nt][3] = p3;
            const int cc = j0 + nt * 8 + ((lane & 3) << 1);
            *(float2*)(arow + (size_t)(i0 + row_lo) * T + cc)     = make_float2(p0, p1);
            *(float2*)(arow + (size_t)(i0 + row_lo + 8) * T + cc) = make_float2(p2, p3);
        }

#pragma unroll
        for (int kg = 0; kg < 8; ++kg) {
            const int f0 = 2 * kg, f1 = 2 * kg + 1;
            uint32_t ah[4], al[4];
            pack2(c[f0][0], c[f0][1], ah[0], al[0]);
            pack2(c[f0][2], c[f0][3], ah[1], al[1]);
            pack2(c[f1][0], c[f1][1], ah[2], al[2]);
            pack2(c[f1][2], c[f1][3], ah[3], al[3]);
            const int kr = kg * 16 + (lane & 15);
#pragma unroll
            for (int nt2 = 0; nt2 < 8; ++nt2) {
                uint32_t vh[2], vl[2];
                ldsm_x2_t(vh[0], vh[1], smem_u32(&sVh[bf][kr * FPAD + nt2 * 8]));
                ldsm_x2_t(vl[0], vl[1], smem_u32(&sVl[bf][kr * FPAD + nt2 * 8]));
                mma_bf16(y[nt2], ah, vh);
                mma_bf16(y[nt2], ah, vl);
                mma_bf16(y[nt2], al, vh);
            }
        }
        __syncthreads();
    }

    // ---- Write y ----
#pragma unroll
    for (int nt2 = 0; nt2 < 8; ++nt2) {
        const int r0 = i0 + row_lo;
        float* y0 = g_y + ((size_t)b * T + r0) * DIM + h * HD + nt2 * 8 + ((lane & 3) << 1);
        *(float2*)y0             = make_float2(y[nt2][0], y[nt2][1]);
        *(float2*)(y0 + 8 * DIM) = make_float2(y[nt2][2], y[nt2][3]);
    }

    // ---- Zero-fill att cols [i0+128, T) for this row block ----
    const int start = i0 + 128;
    if (start < T) {
        const int spanv = (T - start) >> 2;
        for (int r = wid; r < 128; r += 8) {
            float* dst = arow + (size_t)(i0 + r) * T + start;
            for (int cq = lane; cq < spanv; cq += 32)
                *(float4*)(dst + cq * 4) = make_float4(0.f, 0.f, 0.f, 0.f);
        }
    }
}

// ===========================================================================
extern "C" void kernel_launch(void* const* d_in, const int* in_sizes, int n_in,
                              void* d_out, int out_size) {
    const float* Q  = (const float*)d_in[0];
    const float* K  = (const float*)d_in[1];
    const float* V  = (const float*)d_in[2];
    const float* Wq = (const float*)d_in[3];
    const float* Wk = (const float*)d_in[4];
    const float* Wv = (const float*)d_in[5];
    const float* Wo = (const float*)d_in[6];
    float* out = (float*)d_out;

    float *gy, *gfb;
    cudaGetSymbolAddress((void**)&gy,  g_y);
    cudaGetSymbolAddress((void**)&gfb, g_att_fb);

    float* att = ((size_t)out_size >= Y_SIZE + ATT_SIZE) ? (out + Y_SIZE) : gfb;

    cudaFuncSetAttribute(fused_attn, cudaFuncAttributeMaxDynamicSharedMemorySize,
                         FUSED_SMEM);

    dim3 thr(256);

    // 1) Merged Q/K/V projections (q pre-scaled by SCALE*log2e)
    dim3 gQKV(NDIM / 128, BT / 128, 3);   // (8, 32, 3)
    gemm_qkv<<<gQKV, thr>>>(Q, K, V, Wq, Wk, Wv);

    // 2) Fused scores + softmax + att + AV (double-buffered cp.async)
    dim3 gFuse(T / 128, B * H);           // (16, 32)
    fused_attn<<<gFuse, thr, FUSED_SMEM>>>(att);

    // 3) out = y @ Wo^T
    dim3 gOut(NDIM / 128, BT / 128);
    gemm_out<<<gOut, thr>>>(gy, Wo, out);
}